// round 2
// baseline (speedup 1.0000x reference)
#include <cuda_runtime.h>

#define NNODES_MAX 100000
#define NEDGES_MAX 1600000
#define NG_MAX     1000

// ---------------- scratch (static device globals; no allocation) ----------------
__device__ int   g_deg[NNODES_MAX];
__device__ float g_dinv[NNODES_MAX];
__device__ int   g_off[NNODES_MAX + 1];
__device__ int   g_cur[NNODES_MAX];
__device__ int   g_csr[NEDGES_MAX];
__device__ int   g_bsum[256];
__device__ int   g_bpref[256];
__device__ float g_y1[NNODES_MAX * 128];   // (x@W1)*dinv[row]
__device__ float g_h1[NNODES_MAX * 128];   // relu(gcn1)
__device__ float g_y2[NNODES_MAX * 64];    // (h1@W2)*dinv[row]
__device__ float g_gsum[NG_MAX * 64];
__device__ int   g_cnt[NG_MAX];

// ---------------- init / degree / counts ----------------
__global__ void k_zero(int n, int G) {
    int i = blockIdx.x * blockDim.x + threadIdx.x;
    if (i < n) g_deg[i] = 0;
    if (i < G * 64) g_gsum[i] = 0.f;
    if (i < G) g_cnt[i] = 0;
}

__global__ void k_count(const int* __restrict__ dst, int E,
                        const int* __restrict__ batch, int n) {
    int stride = gridDim.x * blockDim.x;
    for (int i = blockIdx.x * blockDim.x + threadIdx.x; i < E; i += stride)
        atomicAdd(&g_deg[dst[i]], 1);
    for (int i = blockIdx.x * blockDim.x + threadIdx.x; i < n; i += stride)
        atomicAdd(&g_cnt[batch[i]], 1);
}

__global__ void k_dinv(int n) {
    int i = blockIdx.x * blockDim.x + threadIdx.x;
    if (i < n) g_dinv[i] = rsqrtf((float)(g_deg[i] + 1));   // +1 self-loop; deg>=1 always
}

// ---------------- prefix scan (2-level) for CSR offsets ----------------
__global__ void k_scan1(int n) {
    __shared__ int wsum[32];
    int i = blockIdx.x * 1024 + threadIdx.x;
    int lane = threadIdx.x & 31, wid = threadIdx.x >> 5;
    int x = (i < n) ? g_deg[i] : 0;
    #pragma unroll
    for (int o = 1; o < 32; o <<= 1) {
        int y = __shfl_up_sync(0xffffffffu, x, o);
        if (lane >= o) x += y;
    }
    if (lane == 31) wsum[wid] = x;
    __syncthreads();
    if (wid == 0) {
        int w = wsum[lane];
        #pragma unroll
        for (int o = 1; o < 32; o <<= 1) {
            int y = __shfl_up_sync(0xffffffffu, w, o);
            if (lane >= o) w += y;
        }
        wsum[lane] = w;
    }
    __syncthreads();
    int incl = x + (wid > 0 ? wsum[wid - 1] : 0);
    if (i < n) g_off[i + 1] = incl;
    if (threadIdx.x == 1023) g_bsum[blockIdx.x] = incl;
}

__global__ void k_scan2(int nb) {
    if (threadIdx.x == 0) {
        int s = 0;
        for (int b = 0; b < nb; b++) { int t = g_bsum[b]; g_bpref[b] = s; s += t; }
    }
}

__global__ void k_scan3(int n) {
    int i = blockIdx.x * blockDim.x + threadIdx.x;
    if (i == 0) g_off[0] = 0;
    if (i < n) g_off[i + 1] += g_bpref[i >> 10];
}

__global__ void k_cursor(int n) {
    int i = blockIdx.x * blockDim.x + threadIdx.x;
    if (i < n) g_cur[i] = g_off[i];
}

__global__ void k_fill(const int* __restrict__ src, const int* __restrict__ dst, int E) {
    int stride = gridDim.x * blockDim.x;
    for (int e = blockIdx.x * blockDim.x + threadIdx.x; e < E; e += stride) {
        int pos = atomicAdd(&g_cur[dst[e]], 1);
        g_csr[pos] = src[e];
    }
}

// ---------------- fp32 tiled GEMM with dinv-scaled epilogue ----------------
// C[m][n] = (sum_k A[m][k]*B[k][n]) * g_dinv[m]
template<int BM, int BN, int BK, int TM, int TN>
__global__ __launch_bounds__(256)
void gemm_scale(const float* __restrict__ A, const float* __restrict__ B,
                float* __restrict__ C, int M, int N, int K) {
    __shared__ float As[BM][BK + 1];
    __shared__ float Bs[BK][BN];
    const int tid = threadIdx.x;
    constexpr int NT = (BM / TM) * (BN / TN);   // 256
    const int m0 = blockIdx.y * BM;
    const int tx = tid % (BN / TN);
    const int ty = tid / (BN / TN);

    float acc[TM][TN];
    #pragma unroll
    for (int i = 0; i < TM; i++)
        #pragma unroll
        for (int j = 0; j < TN; j++) acc[i][j] = 0.f;

    for (int k0 = 0; k0 < K; k0 += BK) {
        #pragma unroll
        for (int f = tid; f < BM * BK / 4; f += NT) {
            int r = f / (BK / 4);
            int c = (f % (BK / 4)) * 4;
            int gm = m0 + r;
            float4 v = make_float4(0.f, 0.f, 0.f, 0.f);
            if (gm < M) v = *(const float4*)&A[(long)gm * K + k0 + c];
            As[r][c] = v.x; As[r][c + 1] = v.y; As[r][c + 2] = v.z; As[r][c + 3] = v.w;
        }
        #pragma unroll
        for (int f = tid; f < BK * BN / 4; f += NT) {
            int r = f / (BN / 4);
            int c = (f % (BN / 4)) * 4;
            *(float4*)&Bs[r][c] = *(const float4*)&B[(long)(k0 + r) * N + c];
        }
        __syncthreads();
        #pragma unroll
        for (int k = 0; k < BK; k++) {
            float a[TM], b[TN];
            #pragma unroll
            for (int i = 0; i < TM; i++) a[i] = As[ty * TM + i][k];
            #pragma unroll
            for (int j = 0; j < TN; j++) b[j] = Bs[k][tx * TN + j];
            #pragma unroll
            for (int i = 0; i < TM; i++)
                #pragma unroll
                for (int j = 0; j < TN; j++)
                    acc[i][j] += a[i] * b[j];
        }
        __syncthreads();
    }
    #pragma unroll
    for (int i = 0; i < TM; i++) {
        int gm = m0 + ty * TM + i;
        if (gm < M) {
            float s = g_dinv[gm];
            #pragma unroll
            for (int j = 0; j < TN; j += 4) {
                float4 v;
                v.x = acc[i][j] * s; v.y = acc[i][j + 1] * s;
                v.z = acc[i][j + 2] * s; v.w = acc[i][j + 3] * s;
                *(float4*)&C[(long)gm * N + tx * TN + j] = v;
            }
        }
    }
}

// ---------------- aggregation ----------------
// h1[d] = relu(dinv[d] * (y1[d] + sum_{src in N(d)} y1[src]) + b1)
__global__ void k_agg1(const float* __restrict__ b1) {
    int d = blockIdx.x;
    int t = threadIdx.x;
    float acc = g_y1[d * 128 + t];                  // self-loop term (y already *dinv[src])
    int e0 = g_off[d], e1 = g_off[d + 1];
    for (int e = e0; e < e1; e++) {
        int s = g_csr[e];
        acc += g_y1[s * 128 + t];
    }
    float v = acc * g_dinv[d] + b1[t];
    g_h1[d * 128 + t] = fmaxf(v, 0.f);
}

// layer-2 aggregation fused with graph mean-pool numerator
__global__ void k_agg2(const float* __restrict__ b2, const int* __restrict__ batch) {
    int d = blockIdx.x;
    int t = threadIdx.x;
    float acc = g_y2[d * 64 + t];
    int e0 = g_off[d], e1 = g_off[d + 1];
    for (int e = e0; e < e1; e++)
        acc += g_y2[g_csr[e] * 64 + t];
    float v = acc * g_dinv[d] + b2[t];
    atomicAdd(&g_gsum[batch[d] * 64 + t], v);
}

// ---------------- head: mean, fc, log_softmax ----------------
__global__ void k_final(const float* __restrict__ fcW, const float* __restrict__ fcb,
                        float* __restrict__ out, int G) {
    int g = blockIdx.x * blockDim.x + threadIdx.x;
    if (g >= G) return;
    float inv = 1.f / fmaxf((float)g_cnt[g], 1.f);
    float l0 = fcb[0], l1 = fcb[1], l2 = fcb[2], l3 = fcb[3];
    #pragma unroll 8
    for (int f = 0; f < 64; f++) {
        float v = g_gsum[g * 64 + f] * inv;
        l0 += v * fcW[f * 4 + 0];
        l1 += v * fcW[f * 4 + 1];
        l2 += v * fcW[f * 4 + 2];
        l3 += v * fcW[f * 4 + 3];
    }
    float m = fmaxf(fmaxf(l0, l1), fmaxf(l2, l3));
    float s = expf(l0 - m) + expf(l1 - m) + expf(l2 - m) + expf(l3 - m);
    float ls = m + logf(s);
    out[g * 4 + 0] = l0 - ls;
    out[g * 4 + 1] = l1 - ls;
    out[g * 4 + 2] = l2 - ls;
    out[g * 4 + 3] = l3 - ls;
}

// ---------------- launch ----------------
extern "C" void kernel_launch(void* const* d_in, const int* in_sizes, int n_in,
                              void* d_out, int out_size) {
    const float* x     = (const float*)d_in[0];
    const int*   ei    = (const int*)d_in[1];
    const int*   batch = (const int*)d_in[2];
    const float* W1    = (const float*)d_in[3];
    const float* b1    = (const float*)d_in[4];
    const float* W2    = (const float*)d_in[5];
    const float* b2    = (const float*)d_in[6];
    const float* fcW   = (const float*)d_in[7];
    const float* fcb   = (const float*)d_in[8];
    float* out = (float*)d_out;

    const int N = in_sizes[0] / 256;
    const int E = in_sizes[1] / 2;
    const int G = out_size / 4;
    const int* src = ei;
    const int* dst = ei + E;

    float *y1p, *h1p, *y2p;
    cudaGetSymbolAddress((void**)&y1p, g_y1);
    cudaGetSymbolAddress((void**)&h1p, g_h1);
    cudaGetSymbolAddress((void**)&y2p, g_y2);

    const int nb = (N + 255) / 256;
    const int nscan = (N + 1023) / 1024;

    k_zero<<<nb, 256>>>(N, G);
    k_count<<<1184, 256>>>(dst, E, batch, N);
    k_dinv<<<nb, 256>>>(N);
    k_scan1<<<nscan, 1024>>>(N);
    k_scan2<<<1, 32>>>(nscan);
    k_scan3<<<nb, 256>>>(N);
    k_cursor<<<nb, 256>>>(N);
    k_fill<<<1184, 256>>>(src, dst, E);

    dim3 gg(1, (N + 127) / 128);
    gemm_scale<128, 128, 16, 8, 8><<<gg, 256>>>(x, W1, y1p, N, 128, 256);
    k_agg1<<<N, 128>>>(b1);
    gemm_scale<128, 64, 16, 8, 4><<<gg, 256>>>(h1p, W2, y2p, N, 64, 128);
    k_agg2<<<N, 64>>>(b2, batch);
    k_final<<<(G + 127) / 128, 128>>>(fcW, fcb, out, G);
}

// round 3
// speedup vs baseline: 1.2410x; 1.2410x over previous
#include <cuda_runtime.h>

#define NNODES_MAX 100000
#define NEDGES_MAX 1600000
#define NG_MAX     1000

// ---------------- scratch (static device globals; no allocation) ----------------
__device__ int   g_deg[NNODES_MAX];
__device__ float g_dinv[NNODES_MAX];
__device__ int   g_off[NNODES_MAX + 1];
__device__ int   g_cur[NNODES_MAX];
__device__ int   g_csr[NEDGES_MAX];
__device__ int   g_bsum[256];
__device__ int   g_bpref[256];
__device__ float g_y1[NNODES_MAX * 128];   // (x@W1)*dinv[row]
__device__ float g_h1[NNODES_MAX * 128];   // relu(gcn1); later reused as h2 (64 feats)
__device__ float g_y2[NNODES_MAX * 64];    // (h1@W2)*dinv[row]

// ---------------- init / degree ----------------
__global__ void k_zero(int n) {
    int i = blockIdx.x * blockDim.x + threadIdx.x;
    if (i < n) g_deg[i] = 0;
}

__global__ void k_count(const int* __restrict__ dst, int E) {
    int stride = gridDim.x * blockDim.x;
    for (int i = blockIdx.x * blockDim.x + threadIdx.x; i < E; i += stride)
        atomicAdd(&g_deg[dst[i]], 1);
}

// ---------------- prefix scan (2-level) for CSR offsets; dinv fused ----------------
__global__ void k_scan1(int n) {
    __shared__ int wsum[32];
    int i = blockIdx.x * 1024 + threadIdx.x;
    int lane = threadIdx.x & 31, wid = threadIdx.x >> 5;
    int d = (i < n) ? g_deg[i] : 0;
    if (i < n) g_dinv[i] = rsqrtf((float)(d + 1));   // +1 self-loop
    int x = d;
    #pragma unroll
    for (int o = 1; o < 32; o <<= 1) {
        int y = __shfl_up_sync(0xffffffffu, x, o);
        if (lane >= o) x += y;
    }
    if (lane == 31) wsum[wid] = x;
    __syncthreads();
    if (wid == 0) {
        int w = wsum[lane];
        #pragma unroll
        for (int o = 1; o < 32; o <<= 1) {
            int y = __shfl_up_sync(0xffffffffu, w, o);
            if (lane >= o) w += y;
        }
        wsum[lane] = w;
    }
    __syncthreads();
    int incl = x + (wid > 0 ? wsum[wid - 1] : 0);
    if (i < n) g_off[i + 1] = incl;
    if (threadIdx.x == 1023) g_bsum[blockIdx.x] = incl;
}

__global__ void k_scan2(int nb) {
    if (threadIdx.x == 0) {
        int s = 0;
        for (int b = 0; b < nb; b++) { int t = g_bsum[b]; g_bpref[b] = s; s += t; }
    }
}

// adds block prefixes; also initializes CSR fill cursors
__global__ void k_scan3(int n) {
    int i = blockIdx.x * blockDim.x + threadIdx.x;
    if (i == 0) { g_off[0] = 0; g_cur[0] = 0; }
    if (i < n) {
        int v = g_off[i + 1] + g_bpref[i >> 10];
        g_off[i + 1] = v;
        if (i + 1 < n) g_cur[i + 1] = v;
    }
}

__global__ void k_fill(const int* __restrict__ src, const int* __restrict__ dst, int E) {
    int stride = gridDim.x * blockDim.x;
    for (int e = blockIdx.x * blockDim.x + threadIdx.x; e < E; e += stride) {
        int pos = atomicAdd(&g_cur[dst[e]], 1);
        g_csr[pos] = src[e];
    }
}

// ---------------- 3xTF32 tensor-core GEMM, dinv-scaled epilogue ----------------
__device__ __forceinline__ unsigned tf32cvt(float x) {
    unsigned r;
    asm("cvt.rna.tf32.f32 %0, %1;" : "=r"(r) : "f"(x));
    return r;
}

__device__ __forceinline__ void mma8(float c[4], unsigned a0, unsigned a1, unsigned a2,
                                     unsigned a3, unsigned b0, unsigned b1) {
    asm("mma.sync.aligned.m16n8k8.row.col.f32.tf32.tf32.f32 "
        "{%0,%1,%2,%3}, {%4,%5,%6,%7}, {%8,%9}, {%0,%1,%2,%3};"
        : "+f"(c[0]), "+f"(c[1]), "+f"(c[2]), "+f"(c[3])
        : "r"(a0), "r"(a1), "r"(a2), "r"(a3), "r"(b0), "r"(b1));
}

// C[m][n] = (sum_k A[m][k]*B[k][n]) * g_dinv[m].   BM=128, BK=32, BN = N (128 or 64).
template<int BN>
__global__ __launch_bounds__(256)
void gemm_tf32(const float* __restrict__ A, const float* __restrict__ B,
               float* __restrict__ C, int M, int K) {
    constexpr int LDA = 36;        // BK + 4 -> conflict-free A frags
    constexpr int LDB = BN + 8;    // conflict-free B frags
    constexpr int NT  = BN / 32;   // n-tiles (8 wide) per warp
    __shared__ float As[128 * LDA];
    __shared__ float Bs[32 * LDB];

    const int tid  = threadIdx.x;
    const int warp = tid >> 5, lane = tid & 31;
    const int gq   = lane >> 2, tig = lane & 3;
    const int wm   = (warp & 1) * 64;
    const int wn   = (warp >> 1) * (BN / 4);
    const int m0   = blockIdx.x * 128;

    float acc[4][NT][4];
    #pragma unroll
    for (int mt = 0; mt < 4; mt++)
        #pragma unroll
        for (int nt = 0; nt < NT; nt++)
            #pragma unroll
            for (int q = 0; q < 4; q++) acc[mt][nt][q] = 0.f;

    for (int k0 = 0; k0 < K; k0 += 32) {
        #pragma unroll
        for (int it = 0; it < 4; it++) {          // A: 128x32 floats
            int idx = it * 256 + tid;
            int r = idx >> 3;
            int c = (idx & 7) * 4;
            int gm = m0 + r;
            float4 v = make_float4(0.f, 0.f, 0.f, 0.f);
            if (gm < M) v = *(const float4*)&A[(size_t)gm * K + k0 + c];
            *(float4*)&As[r * LDA + c] = v;
        }
        #pragma unroll
        for (int it = 0; it < NT; it++) {         // B: 32xBN floats
            int idx = it * 256 + tid;
            int r = idx / (BN / 4);
            int c = (idx % (BN / 4)) * 4;
            *(float4*)&Bs[r * LDB + c] = *(const float4*)&B[(size_t)(k0 + r) * BN + c];
        }
        __syncthreads();
        #pragma unroll
        for (int ks = 0; ks < 4; ks++) {
            const int kb = ks * 8;
            unsigned bh[NT][2], bl[NT][2];
            #pragma unroll
            for (int nt = 0; nt < NT; nt++) {
                int col = wn + nt * 8 + gq;
                float f0 = Bs[(kb + tig) * LDB + col];
                float f1 = Bs[(kb + tig + 4) * LDB + col];
                bh[nt][0] = tf32cvt(f0);
                bl[nt][0] = tf32cvt(f0 - __uint_as_float(bh[nt][0]));
                bh[nt][1] = tf32cvt(f1);
                bl[nt][1] = tf32cvt(f1 - __uint_as_float(bh[nt][1]));
            }
            #pragma unroll
            for (int mt = 0; mt < 4; mt++) {
                int row = wm + mt * 16 + gq;
                float a0 = As[row * LDA + kb + tig];
                float a1 = As[(row + 8) * LDA + kb + tig];
                float a2 = As[row * LDA + kb + tig + 4];
                float a3 = As[(row + 8) * LDA + kb + tig + 4];
                unsigned h0 = tf32cvt(a0), h1 = tf32cvt(a1), h2 = tf32cvt(a2), h3 = tf32cvt(a3);
                unsigned l0 = tf32cvt(a0 - __uint_as_float(h0));
                unsigned l1 = tf32cvt(a1 - __uint_as_float(h1));
                unsigned l2 = tf32cvt(a2 - __uint_as_float(h2));
                unsigned l3 = tf32cvt(a3 - __uint_as_float(h3));
                #pragma unroll
                for (int nt = 0; nt < NT; nt++) {
                    mma8(acc[mt][nt], h0, h1, h2, h3, bh[nt][0], bh[nt][1]);
                    mma8(acc[mt][nt], l0, l1, l2, l3, bh[nt][0], bh[nt][1]);
                    mma8(acc[mt][nt], h0, h1, h2, h3, bl[nt][0], bl[nt][1]);
                }
            }
        }
        __syncthreads();
    }

    #pragma unroll
    for (int mt = 0; mt < 4; mt++) {
        int r0 = m0 + wm + mt * 16 + gq;
        int r1 = r0 + 8;
        #pragma unroll
        for (int nt = 0; nt < NT; nt++) {
            int col = wn + nt * 8 + 2 * tig;
            if (r0 < M) {
                float s = g_dinv[r0];
                float2 v = make_float2(acc[mt][nt][0] * s, acc[mt][nt][1] * s);
                *(float2*)&C[(size_t)r0 * BN + col] = v;
            }
            if (r1 < M) {
                float s = g_dinv[r1];
                float2 v = make_float2(acc[mt][nt][2] * s, acc[mt][nt][3] * s);
                *(float2*)&C[(size_t)r1 * BN + col] = v;
            }
        }
    }
}

// ---------------- aggregation (warp per node, 4-edge MLP unroll) ----------------
// h1[d] = relu(dinv[d] * (y1[d] + sum_{s in N(d)} y1[s]) + b1),  128 feats (float4/lane)
__global__ __launch_bounds__(256)
void k_agg1(const float* __restrict__ b1, int N) {
    int d = blockIdx.x * 8 + (threadIdx.x >> 5);
    if (d >= N) return;
    int l = threadIdx.x & 31;
    const float4* y = (const float4*)g_y1;
    float4 acc = y[d * 32 + l];
    int e = g_off[d], e1 = g_off[d + 1];
    for (; e + 4 <= e1; e += 4) {
        int s0 = g_csr[e], s1 = g_csr[e + 1], s2 = g_csr[e + 2], s3 = g_csr[e + 3];
        float4 v0 = y[s0 * 32 + l];
        float4 v1 = y[s1 * 32 + l];
        float4 v2 = y[s2 * 32 + l];
        float4 v3 = y[s3 * 32 + l];
        acc.x += v0.x + v1.x + v2.x + v3.x;
        acc.y += v0.y + v1.y + v2.y + v3.y;
        acc.z += v0.z + v1.z + v2.z + v3.z;
        acc.w += v0.w + v1.w + v2.w + v3.w;
    }
    for (; e < e1; e++) {
        float4 v = y[g_csr[e] * 32 + l];
        acc.x += v.x; acc.y += v.y; acc.z += v.z; acc.w += v.w;
    }
    float s = g_dinv[d];
    const float4 b = ((const float4*)b1)[l];
    float4 o;
    o.x = fmaxf(acc.x * s + b.x, 0.f);
    o.y = fmaxf(acc.y * s + b.y, 0.f);
    o.z = fmaxf(acc.z * s + b.z, 0.f);
    o.w = fmaxf(acc.w * s + b.w, 0.f);
    ((float4*)g_h1)[d * 32 + l] = o;
}

// h2[d] = dinv[d] * (y2[d] + sum y2[s]) + b2,  64 feats (float2/lane); h2 reuses g_h1
__global__ __launch_bounds__(256)
void k_agg2(const float* __restrict__ b2, int N) {
    int d = blockIdx.x * 8 + (threadIdx.x >> 5);
    if (d >= N) return;
    int l = threadIdx.x & 31;
    const float2* y = (const float2*)g_y2;
    float2 acc = y[d * 32 + l];
    int e = g_off[d], e1 = g_off[d + 1];
    for (; e + 4 <= e1; e += 4) {
        int s0 = g_csr[e], s1 = g_csr[e + 1], s2 = g_csr[e + 2], s3 = g_csr[e + 3];
        float2 v0 = y[s0 * 32 + l];
        float2 v1 = y[s1 * 32 + l];
        float2 v2 = y[s2 * 32 + l];
        float2 v3 = y[s3 * 32 + l];
        acc.x += v0.x + v1.x + v2.x + v3.x;
        acc.y += v0.y + v1.y + v2.y + v3.y;
    }
    for (; e < e1; e++) {
        float2 v = y[g_csr[e] * 32 + l];
        acc.x += v.x; acc.y += v.y;
    }
    float s = g_dinv[d];
    const float2 b = ((const float2*)b2)[l];
    float2 o = make_float2(acc.x * s + b.x, acc.y * s + b.y);
    ((float2*)g_h1)[d * 32 + l] = o;
}

// ---------------- fused head: per-graph mean-pool + fc + log_softmax ----------------
// batch is sorted, so each graph's nodes form a contiguous range (binary search).
__global__ __launch_bounds__(256)
void k_head(const int* __restrict__ batch, const float* __restrict__ fcW,
            const float* __restrict__ fcb, float* __restrict__ out, int N) {
    __shared__ int s_lo, s_hi;
    __shared__ float s_red[256];
    __shared__ float s_mean[64];
    __shared__ float s_logit[4];
    const int gph = blockIdx.x;
    const int tid = threadIdx.x;
    if (tid == 0) {
        int lo = 0, hi = N;
        while (lo < hi) { int m = (lo + hi) >> 1; if (batch[m] < gph) lo = m + 1; else hi = m; }
        s_lo = lo;
        int lo2 = lo, hi2 = N;
        while (lo2 < hi2) { int m = (lo2 + hi2) >> 1; if (batch[m] < gph + 1) lo2 = m + 1; else hi2 = m; }
        s_hi = lo2;
    }
    __syncthreads();
    const int lo = s_lo, hi = s_hi;
    const float inv = 1.f / fmaxf((float)(hi - lo), 1.f);
    const int f = tid & 63, sub = tid >> 6;
    const float* h2 = g_h1;   // reused buffer
    float sum = 0.f;
    for (int i = lo + sub; i < hi; i += 4) sum += h2[(size_t)i * 64 + f];
    s_red[tid] = sum;
    __syncthreads();
    if (tid < 64) {
        float t = s_red[tid] + s_red[tid + 64] + s_red[tid + 128] + s_red[tid + 192];
        s_mean[tid] = t * inv;
    }
    __syncthreads();
    if (tid < 4) {
        float l = fcb[tid];
        #pragma unroll 8
        for (int k = 0; k < 64; k++) l += s_mean[k] * fcW[k * 4 + tid];
        s_logit[tid] = l;
    }
    __syncthreads();
    if (tid == 0) {
        float l0 = s_logit[0], l1 = s_logit[1], l2 = s_logit[2], l3 = s_logit[3];
        float m = fmaxf(fmaxf(l0, l1), fmaxf(l2, l3));
        float s = expf(l0 - m) + expf(l1 - m) + expf(l2 - m) + expf(l3 - m);
        float ls = m + logf(s);
        out[gph * 4 + 0] = l0 - ls;
        out[gph * 4 + 1] = l1 - ls;
        out[gph * 4 + 2] = l2 - ls;
        out[gph * 4 + 3] = l3 - ls;
    }
}

// ---------------- launch ----------------
extern "C" void kernel_launch(void* const* d_in, const int* in_sizes, int n_in,
                              void* d_out, int out_size) {
    const float* x     = (const float*)d_in[0];
    const int*   ei    = (const int*)d_in[1];
    const int*   batch = (const int*)d_in[2];
    const float* W1    = (const float*)d_in[3];
    const float* b1    = (const float*)d_in[4];
    const float* W2    = (const float*)d_in[5];
    const float* b2    = (const float*)d_in[6];
    const float* fcW   = (const float*)d_in[7];
    const float* fcb   = (const float*)d_in[8];
    float* out = (float*)d_out;

    const int N = in_sizes[0] / 256;
    const int E = in_sizes[1] / 2;
    const int G = out_size / 4;
    const int* src = ei;
    const int* dst = ei + E;

    float *y1p, *h1p, *y2p;
    cudaGetSymbolAddress((void**)&y1p, g_y1);
    cudaGetSymbolAddress((void**)&h1p, g_h1);
    cudaGetSymbolAddress((void**)&y2p, g_y2);

    const int nb    = (N + 255) / 256;
    const int nscan = (N + 1023) / 1024;
    const int gm    = (N + 127) / 128;
    const int ga    = (N + 7) / 8;

    k_zero<<<nb, 256>>>(N);
    k_count<<<1184, 256>>>(dst, E);
    k_scan1<<<nscan, 1024>>>(N);
    k_scan2<<<1, 32>>>(nscan);
    k_scan3<<<nb, 256>>>(N);
    k_fill<<<1184, 256>>>(src, dst, E);

    gemm_tf32<128><<<gm, 256>>>(x, W1, y1p, N, 256);
    k_agg1<<<ga, 256>>>(b1, N);
    gemm_tf32<64><<<gm, 256>>>(h1p, W2, y2p, N, 128);
    k_agg2<<<ga, 256>>>(b2, N);
    k_head<<<G, 256>>>(batch, fcW, fcb, out, N);
}

// round 4
// speedup vs baseline: 1.5448x; 1.2448x over previous
#include <cuda_runtime.h>
#include <cuda_fp16.h>

#define NNODES_MAX 100000
#define NEDGES_MAX 1600000
#define NG_MAX     1000

// ---------------- scratch (static device globals; no allocation) ----------------
__device__ int   g_deg[NNODES_MAX];
__device__ float g_dinv[NNODES_MAX];
__device__ int   g_off[NNODES_MAX + 1];
__device__ int   g_cur[NNODES_MAX];
__device__ int   g_csr[NEDGES_MAX];
__device__ int   g_bsum[256];
__device__ int   g_bpref[256];
// g_buf1: y1 as half [N][128]  (layer1 gemm out), later h2 as float [N][64]
// g_buf2: h1 as half [N][128]  (layer1 activation, GEMM2 input)
// g_buf3: y2 as half [N][64]   (layer2 gemm out)
__device__ __align__(16) float g_buf1[NNODES_MAX * 128];
__device__ __align__(16) float g_buf2[NNODES_MAX * 64];
__device__ __align__(16) float g_buf3[NNODES_MAX * 32];

// ---------------- init / degree ----------------
__global__ void k_zero(int n) {
    int i = blockIdx.x * blockDim.x + threadIdx.x;
    if (i < n) g_deg[i] = 0;
}

__global__ void k_count(const int* __restrict__ dst, int E) {
    int stride = gridDim.x * blockDim.x;
    for (int i = blockIdx.x * blockDim.x + threadIdx.x; i < E; i += stride)
        atomicAdd(&g_deg[dst[i]], 1);
}

// ---------------- prefix scan (2-level) for CSR offsets; dinv fused ----------------
__global__ void k_scan1(int n) {
    __shared__ int wsum[32];
    int i = blockIdx.x * 1024 + threadIdx.x;
    int lane = threadIdx.x & 31, wid = threadIdx.x >> 5;
    int d = (i < n) ? g_deg[i] : 0;
    if (i < n) g_dinv[i] = rsqrtf((float)(d + 1));   // +1 self-loop
    int x = d;
    #pragma unroll
    for (int o = 1; o < 32; o <<= 1) {
        int y = __shfl_up_sync(0xffffffffu, x, o);
        if (lane >= o) x += y;
    }
    if (lane == 31) wsum[wid] = x;
    __syncthreads();
    if (wid == 0) {
        int w = wsum[lane];
        #pragma unroll
        for (int o = 1; o < 32; o <<= 1) {
            int y = __shfl_up_sync(0xffffffffu, w, o);
            if (lane >= o) w += y;
        }
        wsum[lane] = w;
    }
    __syncthreads();
    int incl = x + (wid > 0 ? wsum[wid - 1] : 0);
    if (i < n) g_off[i + 1] = incl;
    if (threadIdx.x == 1023) g_bsum[blockIdx.x] = incl;
}

// parallel exclusive scan over block sums (nb <= 128)
__global__ void k_scan2(int nb) {
    __shared__ int ws[4];
    int lane = threadIdx.x & 31, wid = threadIdx.x >> 5;
    int v = (threadIdx.x < nb) ? g_bsum[threadIdx.x] : 0;
    int x = v;
    #pragma unroll
    for (int o = 1; o < 32; o <<= 1) {
        int y = __shfl_up_sync(0xffffffffu, x, o);
        if (lane >= o) x += y;
    }
    if (lane == 31) ws[wid] = x;
    __syncthreads();
    int pre = 0;
    #pragma unroll
    for (int w = 0; w < 4; w++) if (w < wid) pre += ws[w];
    if (threadIdx.x < nb) g_bpref[threadIdx.x] = x - v + pre;   // exclusive
}

// adds block prefixes; also initializes CSR fill cursors
__global__ void k_scan3(int n) {
    int i = blockIdx.x * blockDim.x + threadIdx.x;
    if (i == 0) { g_off[0] = 0; g_cur[0] = 0; }
    if (i < n) {
        int v = g_off[i + 1] + g_bpref[i >> 10];
        g_off[i + 1] = v;
        if (i + 1 < n) g_cur[i + 1] = v;
    }
}

__global__ void k_fill(const int* __restrict__ src, const int* __restrict__ dst, int E) {
    int stride = gridDim.x * blockDim.x;
    for (int e = blockIdx.x * blockDim.x + threadIdx.x; e < E; e += stride) {
        int pos = atomicAdd(&g_cur[dst[e]], 1);
        g_csr[pos] = src[e];
    }
}

// ---------------- tf32 helpers ----------------
__device__ __forceinline__ unsigned tf32cvt(float x) {
    unsigned r;
    asm("cvt.rna.tf32.f32 %0, %1;" : "=r"(r) : "f"(x));
    return r;
}

__device__ __forceinline__ void mma8(float c[4], unsigned a0, unsigned a1, unsigned a2,
                                     unsigned a3, unsigned b0, unsigned b1) {
    asm("mma.sync.aligned.m16n8k8.row.col.f32.tf32.tf32.f32 "
        "{%0,%1,%2,%3}, {%4,%5,%6,%7}, {%8,%9}, {%0,%1,%2,%3};"
        : "+f"(c[0]), "+f"(c[1]), "+f"(c[2]), "+f"(c[3])
        : "r"(a0), "r"(a1), "r"(a2), "r"(a3), "r"(b0), "r"(b1));
}

__device__ __forceinline__ void mma16h(float c[4], unsigned a0, unsigned a1, unsigned a2,
                                       unsigned a3, unsigned b0, unsigned b1) {
    asm("mma.sync.aligned.m16n8k16.row.col.f32.f16.f16.f32 "
        "{%0,%1,%2,%3}, {%4,%5,%6,%7}, {%8,%9}, {%0,%1,%2,%3};"
        : "+f"(c[0]), "+f"(c[1]), "+f"(c[2]), "+f"(c[3])
        : "r"(a0), "r"(a1), "r"(a2), "r"(a3), "r"(b0), "r"(b1));
}

// ---------------- GEMM1: 3xTF32, hi/lo pre-split into smem, half output ----------------
// y1[m][n] = (sum_k x[m][k]*W1[k][n]) * dinv[m],  M=N nodes, K=256, N=128, as half.
__global__ __launch_bounds__(256)
void gemm1_tf32(const float* __restrict__ A, const float* __restrict__ B,
                __half* __restrict__ C, int M) {
    constexpr int K = 256, BN = 128, BK = 16;
    constexpr int LDA = 20, LDB = 136;
    __shared__ unsigned As_h[128 * LDA], As_l[128 * LDA];
    __shared__ unsigned Bs_h[BK * LDB],  Bs_l[BK * LDB];

    const int tid  = threadIdx.x;
    const int warp = tid >> 5, lane = tid & 31;
    const int gq   = lane >> 2, tig = lane & 3;
    const int wm   = (warp & 1) * 64;
    const int wn   = (warp >> 1) * 32;
    const int m0   = blockIdx.x * 128;

    float acc[4][4][4];
    #pragma unroll
    for (int mt = 0; mt < 4; mt++)
        #pragma unroll
        for (int nt = 0; nt < 4; nt++)
            #pragma unroll
            for (int q = 0; q < 4; q++) acc[mt][nt][q] = 0.f;

    for (int k0 = 0; k0 < K; k0 += BK) {
        #pragma unroll
        for (int it = 0; it < 2; it++) {          // A: 128x16 floats
            int idx = it * 256 + tid;
            int r = idx >> 2, c = (idx & 3) * 4;
            int gm = m0 + r;
            float4 v = make_float4(0.f, 0.f, 0.f, 0.f);
            if (gm < M) v = *(const float4*)&A[(size_t)gm * K + k0 + c];
            uint4 h, l;
            h.x = tf32cvt(v.x); l.x = tf32cvt(v.x - __uint_as_float(h.x));
            h.y = tf32cvt(v.y); l.y = tf32cvt(v.y - __uint_as_float(h.y));
            h.z = tf32cvt(v.z); l.z = tf32cvt(v.z - __uint_as_float(h.z));
            h.w = tf32cvt(v.w); l.w = tf32cvt(v.w - __uint_as_float(h.w));
            *(uint4*)&As_h[r * LDA + c] = h;
            *(uint4*)&As_l[r * LDA + c] = l;
        }
        #pragma unroll
        for (int it = 0; it < 2; it++) {          // B: 16x128 floats
            int idx = it * 256 + tid;
            int r = idx >> 5, c = (idx & 31) * 4;
            float4 v = *(const float4*)&B[(size_t)(k0 + r) * BN + c];
            uint4 h, l;
            h.x = tf32cvt(v.x); l.x = tf32cvt(v.x - __uint_as_float(h.x));
            h.y = tf32cvt(v.y); l.y = tf32cvt(v.y - __uint_as_float(h.y));
            h.z = tf32cvt(v.z); l.z = tf32cvt(v.z - __uint_as_float(h.z));
            h.w = tf32cvt(v.w); l.w = tf32cvt(v.w - __uint_as_float(h.w));
            *(uint4*)&Bs_h[r * LDB + c] = h;
            *(uint4*)&Bs_l[r * LDB + c] = l;
        }
        __syncthreads();
        #pragma unroll
        for (int ks = 0; ks < 2; ks++) {
            const int kb = ks * 8;
            unsigned bh[4][2], bl[4][2];
            #pragma unroll
            for (int nt = 0; nt < 4; nt++) {
                int col = wn + nt * 8 + gq;
                bh[nt][0] = Bs_h[(kb + tig) * LDB + col];
                bh[nt][1] = Bs_h[(kb + tig + 4) * LDB + col];
                bl[nt][0] = Bs_l[(kb + tig) * LDB + col];
                bl[nt][1] = Bs_l[(kb + tig + 4) * LDB + col];
            }
            #pragma unroll
            for (int mt = 0; mt < 4; mt++) {
                int row = wm + mt * 16 + gq;
                unsigned h0 = As_h[row * LDA + kb + tig];
                unsigned h1 = As_h[(row + 8) * LDA + kb + tig];
                unsigned h2 = As_h[row * LDA + kb + tig + 4];
                unsigned h3 = As_h[(row + 8) * LDA + kb + tig + 4];
                unsigned l0 = As_l[row * LDA + kb + tig];
                unsigned l1 = As_l[(row + 8) * LDA + kb + tig];
                unsigned l2 = As_l[row * LDA + kb + tig + 4];
                unsigned l3 = As_l[(row + 8) * LDA + kb + tig + 4];
                #pragma unroll
                for (int nt = 0; nt < 4; nt++) {
                    mma8(acc[mt][nt], h0, h1, h2, h3, bh[nt][0], bh[nt][1]);
                    mma8(acc[mt][nt], l0, l1, l2, l3, bh[nt][0], bh[nt][1]);
                    mma8(acc[mt][nt], h0, h1, h2, h3, bl[nt][0], bl[nt][1]);
                }
            }
        }
        __syncthreads();
    }

    #pragma unroll
    for (int mt = 0; mt < 4; mt++) {
        int r0 = m0 + wm + mt * 16 + gq;
        int r1 = r0 + 8;
        #pragma unroll
        for (int nt = 0; nt < 4; nt++) {
            int col = wn + nt * 8 + 2 * tig;
            if (r0 < M) {
                float s = g_dinv[r0];
                *(__half2*)&C[(size_t)r0 * BN + col] =
                    __floats2half2_rn(acc[mt][nt][0] * s, acc[mt][nt][1] * s);
            }
            if (r1 < M) {
                float s = g_dinv[r1];
                *(__half2*)&C[(size_t)r1 * BN + col] =
                    __floats2half2_rn(acc[mt][nt][2] * s, acc[mt][nt][3] * s);
            }
        }
    }
}

// ---------------- GEMM2: fp16 MMA (B split hi+lo), K=128, N=64, half in/out ----------------
// y2[m][n] = (sum_k h1[m][k]*W2[k][n]) * dinv[m]
__global__ __launch_bounds__(256)
void gemm2_f16(const __half* __restrict__ A, const float* __restrict__ B,
               __half* __restrict__ C, int M) {
    constexpr int K = 128, BN = 64, BK = 64;
    constexpr int LDA = 72, LDB = 72;   // halves
    __shared__ __half As[128 * LDA];
    __shared__ __half Bth[BN * LDB], Btl[BN * LDB];   // transposed [n][k]

    const int tid  = threadIdx.x;
    const int warp = tid >> 5, lane = tid & 31;
    const int gq   = lane >> 2, tig = lane & 3;
    const int wm   = (warp & 1) * 64;
    const int wn   = (warp >> 1) * 16;
    const int m0   = blockIdx.x * 128;

    float acc[4][2][4];
    #pragma unroll
    for (int mt = 0; mt < 4; mt++)
        #pragma unroll
        for (int nt = 0; nt < 2; nt++)
            #pragma unroll
            for (int q = 0; q < 4; q++) acc[mt][nt][q] = 0.f;

    for (int k0 = 0; k0 < K; k0 += BK) {
        #pragma unroll
        for (int it = 0; it < 4; it++) {          // A: 128x64 halves
            int idx = it * 256 + tid;
            int r = idx >> 3, c = (idx & 7) * 8;
            int gm = m0 + r;
            uint4 v = make_uint4(0u, 0u, 0u, 0u);
            if (gm < M) v = *(const uint4*)&A[(size_t)gm * K + k0 + c];
            *(uint4*)&As[r * LDA + c] = v;
        }
        #pragma unroll
        for (int it = 0; it < 16; it++) {         // B: 64x64 floats -> transposed half hi/lo
            int idx = it * 256 + tid;
            int rk = idx >> 6, n = idx & 63;
            float v = B[(size_t)(k0 + rk) * BN + n];
            __half h = __float2half_rn(v);
            __half l = __float2half_rn(v - __half2float(h));
            Bth[n * LDB + rk] = h;
            Btl[n * LDB + rk] = l;
        }
        __syncthreads();
        #pragma unroll
        for (int ks = 0; ks < 4; ks++) {
            const int kb = ks * 16;
            unsigned bh[2][2], bl[2][2];
            #pragma unroll
            for (int nt = 0; nt < 2; nt++) {
                int col = wn + nt * 8 + gq;
                bh[nt][0] = *(const unsigned*)&Bth[col * LDB + kb + 2 * tig];
                bh[nt][1] = *(const unsigned*)&Bth[col * LDB + kb + 2 * tig + 8];
                bl[nt][0] = *(const unsigned*)&Btl[col * LDB + kb + 2 * tig];
                bl[nt][1] = *(const unsigned*)&Btl[col * LDB + kb + 2 * tig + 8];
            }
            #pragma unroll
            for (int mt = 0; mt < 4; mt++) {
                int row = wm + mt * 16 + gq;
                unsigned a0 = *(const unsigned*)&As[row * LDA + kb + 2 * tig];
                unsigned a1 = *(const unsigned*)&As[(row + 8) * LDA + kb + 2 * tig];
                unsigned a2 = *(const unsigned*)&As[row * LDA + kb + 2 * tig + 8];
                unsigned a3 = *(const unsigned*)&As[(row + 8) * LDA + kb + 2 * tig + 8];
                #pragma unroll
                for (int nt = 0; nt < 2; nt++) {
                    mma16h(acc[mt][nt], a0, a1, a2, a3, bh[nt][0], bh[nt][1]);
                    mma16h(acc[mt][nt], a0, a1, a2, a3, bl[nt][0], bl[nt][1]);
                }
            }
        }
        __syncthreads();
    }

    #pragma unroll
    for (int mt = 0; mt < 4; mt++) {
        int r0 = m0 + wm + mt * 16 + gq;
        int r1 = r0 + 8;
        #pragma unroll
        for (int nt = 0; nt < 2; nt++) {
            int col = wn + nt * 8 + 2 * tig;
            if (r0 < M) {
                float s = g_dinv[r0];
                *(__half2*)&C[(size_t)r0 * BN + col] =
                    __floats2half2_rn(acc[mt][nt][0] * s, acc[mt][nt][1] * s);
            }
            if (r1 < M) {
                float s = g_dinv[r1];
                *(__half2*)&C[(size_t)r1 * BN + col] =
                    __floats2half2_rn(acc[mt][nt][2] * s, acc[mt][nt][3] * s);
            }
        }
    }
}

// ---------------- aggregation (warp per node, half gathers, fp32 accum) ----------------
// h1[d] = relu(dinv[d]*(y1[d] + sum y1[s]) + b1), 128 feats; y1/h1 half
__global__ __launch_bounds__(256)
void k_agg1(const float* __restrict__ b1, int N) {
    int d = blockIdx.x * 8 + (threadIdx.x >> 5);
    if (d >= N) return;
    int l = threadIdx.x & 31;
    const uint2* y = (const uint2*)g_buf1;       // half[.][128] -> 32 uint2/row
    uint2 u = y[(size_t)d * 32 + l];
    float2 f0 = __half22float2(*(__half2*)&u.x);
    float2 f1 = __half22float2(*(__half2*)&u.y);
    float a0 = f0.x, a1 = f0.y, a2 = f1.x, a3 = f1.y;
    int e = g_off[d], e1 = g_off[d + 1];
    for (; e + 4 <= e1; e += 4) {
        int s0 = g_csr[e], s1 = g_csr[e + 1], s2 = g_csr[e + 2], s3 = g_csr[e + 3];
        uint2 u0 = y[(size_t)s0 * 32 + l];
        uint2 u1 = y[(size_t)s1 * 32 + l];
        uint2 u2 = y[(size_t)s2 * 32 + l];
        uint2 u3 = y[(size_t)s3 * 32 + l];
        float2 p;
        p = __half22float2(*(__half2*)&u0.x); a0 += p.x; a1 += p.y;
        p = __half22float2(*(__half2*)&u0.y); a2 += p.x; a3 += p.y;
        p = __half22float2(*(__half2*)&u1.x); a0 += p.x; a1 += p.y;
        p = __half22float2(*(__half2*)&u1.y); a2 += p.x; a3 += p.y;
        p = __half22float2(*(__half2*)&u2.x); a0 += p.x; a1 += p.y;
        p = __half22float2(*(__half2*)&u2.y); a2 += p.x; a3 += p.y;
        p = __half22float2(*(__half2*)&u3.x); a0 += p.x; a1 += p.y;
        p = __half22float2(*(__half2*)&u3.y); a2 += p.x; a3 += p.y;
    }
    for (; e < e1; e++) {
        uint2 u0 = y[(size_t)g_csr[e] * 32 + l];
        float2 p;
        p = __half22float2(*(__half2*)&u0.x); a0 += p.x; a1 += p.y;
        p = __half22float2(*(__half2*)&u0.y); a2 += p.x; a3 += p.y;
    }
    float s = g_dinv[d];
    const float4 b = ((const float4*)b1)[l];
    uint2 o;
    *(__half2*)&o.x = __floats2half2_rn(fmaxf(a0 * s + b.x, 0.f), fmaxf(a1 * s + b.y, 0.f));
    *(__half2*)&o.y = __floats2half2_rn(fmaxf(a2 * s + b.z, 0.f), fmaxf(a3 * s + b.w, 0.f));
    ((uint2*)g_buf2)[(size_t)d * 32 + l] = o;
}

// h2[d] = dinv[d]*(y2[d] + sum y2[s]) + b2, 64 feats; y2 half -> h2 float (into g_buf1)
__global__ __launch_bounds__(256)
void k_agg2(const float* __restrict__ b2, int N) {
    int d = blockIdx.x * 8 + (threadIdx.x >> 5);
    if (d >= N) return;
    int l = threadIdx.x & 31;
    const __half2* y = (const __half2*)g_buf3;   // half[.][64] -> 32 half2/row
    float2 acc = __half22float2(y[(size_t)d * 32 + l]);
    int e = g_off[d], e1 = g_off[d + 1];
    for (; e + 4 <= e1; e += 4) {
        int s0 = g_csr[e], s1 = g_csr[e + 1], s2 = g_csr[e + 2], s3 = g_csr[e + 3];
        float2 v0 = __half22float2(y[(size_t)s0 * 32 + l]);
        float2 v1 = __half22float2(y[(size_t)s1 * 32 + l]);
        float2 v2 = __half22float2(y[(size_t)s2 * 32 + l]);
        float2 v3 = __half22float2(y[(size_t)s3 * 32 + l]);
        acc.x += v0.x + v1.x + v2.x + v3.x;
        acc.y += v0.y + v1.y + v2.y + v3.y;
    }
    for (; e < e1; e++) {
        float2 v = __half22float2(y[(size_t)g_csr[e] * 32 + l]);
        acc.x += v.x; acc.y += v.y;
    }
    float s = g_dinv[d];
    const float2 b = ((const float2*)b2)[l];
    ((float2*)g_buf1)[(size_t)d * 32 + l] = make_float2(acc.x * s + b.x, acc.y * s + b.y);
}

// ---------------- fused head: per-graph mean-pool + fc + log_softmax ----------------
__global__ __launch_bounds__(256)
void k_head(const int* __restrict__ batch, const float* __restrict__ fcW,
            const float* __restrict__ fcb, float* __restrict__ out, int N) {
    __shared__ int s_lo, s_hi;
    __shared__ float s_red[256];
    __shared__ float s_mean[64];
    __shared__ float s_logit[4];
    const int gph = blockIdx.x;
    const int tid = threadIdx.x;
    if (tid == 0) {
        int lo = 0, hi = N;
        while (lo < hi) { int m = (lo + hi) >> 1; if (batch[m] < gph) lo = m + 1; else hi = m; }
        s_lo = lo;
        int lo2 = lo, hi2 = N;
        while (lo2 < hi2) { int m = (lo2 + hi2) >> 1; if (batch[m] < gph + 1) lo2 = m + 1; else hi2 = m; }
        s_hi = lo2;
    }
    __syncthreads();
    const int lo = s_lo, hi = s_hi;
    const float inv = 1.f / fmaxf((float)(hi - lo), 1.f);
    const int f = tid & 63, sub = tid >> 6;
    const float* h2 = g_buf1;
    float sum = 0.f;
    for (int i = lo + sub; i < hi; i += 4) sum += h2[(size_t)i * 64 + f];
    s_red[tid] = sum;
    __syncthreads();
    if (tid < 64) {
        float t = s_red[tid] + s_red[tid + 64] + s_red[tid + 128] + s_red[tid + 192];
        s_mean[tid] = t * inv;
    }
    __syncthreads();
    if (tid < 4) {
        float l = fcb[tid];
        #pragma unroll 8
        for (int k = 0; k < 64; k++) l += s_mean[k] * fcW[k * 4 + tid];
        s_logit[tid] = l;
    }
    __syncthreads();
    if (tid == 0) {
        float l0 = s_logit[0], l1 = s_logit[1], l2 = s_logit[2], l3 = s_logit[3];
        float m = fmaxf(fmaxf(l0, l1), fmaxf(l2, l3));
        float s = expf(l0 - m) + expf(l1 - m) + expf(l2 - m) + expf(l3 - m);
        float ls = m + logf(s);
        out[gph * 4 + 0] = l0 - ls;
        out[gph * 4 + 1] = l1 - ls;
        out[gph * 4 + 2] = l2 - ls;
        out[gph * 4 + 3] = l3 - ls;
    }
}

// ---------------- launch ----------------
extern "C" void kernel_launch(void* const* d_in, const int* in_sizes, int n_in,
                              void* d_out, int out_size) {
    const float* x     = (const float*)d_in[0];
    const int*   ei    = (const int*)d_in[1];
    const int*   batch = (const int*)d_in[2];
    const float* W1    = (const float*)d_in[3];
    const float* b1    = (const float*)d_in[4];
    const float* W2    = (const float*)d_in[5];
    const float* b2    = (const float*)d_in[6];
    const float* fcW   = (const float*)d_in[7];
    const float* fcb   = (const float*)d_in[8];
    float* out = (float*)d_out;

    const int N = in_sizes[0] / 256;
    const int E = in_sizes[1] / 2;
    const int G = out_size / 4;
    const int* src = ei;
    const int* dst = ei + E;

    float *b1p, *b2p, *b3p;
    cudaGetSymbolAddress((void**)&b1p, g_buf1);
    cudaGetSymbolAddress((void**)&b2p, g_buf2);
    cudaGetSymbolAddress((void**)&b3p, g_buf3);
    __half* y1h = (__half*)b1p;
    __half* h1h = (__half*)b2p;
    __half* y2h = (__half*)b3p;

    const int nb    = (N + 255) / 256;
    const int nscan = (N + 1023) / 1024;
    const int gm    = (N + 127) / 128;
    const int ga    = (N + 7) / 8;

    k_zero<<<nb, 256>>>(N);
    k_count<<<1184, 256>>>(dst, E);
    k_scan1<<<nscan, 1024>>>(N);
    k_scan2<<<1, 128>>>(nscan);
    k_scan3<<<nb, 256>>>(N);
    k_fill<<<1184, 256>>>(src, dst, E);

    gemm1_tf32<<<gm, 256>>>(x, W1, y1h, N);
    k_agg1<<<ga, 256>>>(b1, N);
    gemm2_f16<<<gm, 256>>>(h1h, W2, y2h, N);
    k_agg2<<<ga, 256>>>(b2, N);
    k_head<<<G, 256>>>(batch, fcW, fcb, out, N);
}

// round 5
// speedup vs baseline: 1.8507x; 1.1980x over previous
#include <cuda_runtime.h>
#include <cuda_fp16.h>

#define NNODES_MAX 100000
#define NEDGES_MAX 1600000
#define NG_MAX     1000

// ---------------- scratch (static device globals; no allocation) ----------------
__device__ int   g_deg[NNODES_MAX];
__device__ float g_dinv[NNODES_MAX];
__device__ int   g_off[NNODES_MAX + 1];
__device__ int   g_cur[NNODES_MAX];
__device__ int   g_csr[NEDGES_MAX];
__device__ int   g_bsum[256];
__device__ int   g_bpref[256];
// g_buf1: y1 as half [N][128] (gemm1 out, unscaled), later h2 as float [N][64]
// g_buf2: h1 as half [N][128]
// g_buf3: y2 as half [N][64]
__device__ __align__(16) float g_buf1[NNODES_MAX * 128];
__device__ __align__(16) float g_buf2[NNODES_MAX * 64];
__device__ __align__(16) float g_buf3[NNODES_MAX * 32];
// pre-split transposed weights: [n][k] half hi/lo
__device__ __align__(16) __half g_W1th[128 * 256], g_W1tl[128 * 256];
__device__ __align__(16) __half g_W2th[64 * 128],  g_W2tl[64 * 128];

// ---------------- weight convert (hi/lo split + transpose) ----------------
__global__ void k_wconv(const float* __restrict__ W1, const float* __restrict__ W2) {
    int i = blockIdx.x * blockDim.x + threadIdx.x;
    if (i < 256 * 128) {
        int k = i >> 7, n = i & 127;
        float v = W1[i];
        __half h = __float2half_rn(v);
        g_W1th[n * 256 + k] = h;
        g_W1tl[n * 256 + k] = __float2half_rn(v - __half2float(h));
    } else if (i < 256 * 128 + 128 * 64) {
        int j = i - 256 * 128;
        int k = j >> 6, n = j & 63;
        float v = W2[j];
        __half h = __float2half_rn(v);
        g_W2th[n * 128 + k] = h;
        g_W2tl[n * 128 + k] = __float2half_rn(v - __half2float(h));
    }
}

// ---------------- degree / scan / CSR ----------------
__global__ void k_count(const int* __restrict__ dst, int E) {
    int stride = gridDim.x * blockDim.x;
    for (int i = blockIdx.x * blockDim.x + threadIdx.x; i < E; i += stride)
        atomicAdd(&g_deg[dst[i]], 1);
}

__global__ void k_scan1(int n) {
    __shared__ int wsum[32];
    int i = blockIdx.x * 1024 + threadIdx.x;
    int lane = threadIdx.x & 31, wid = threadIdx.x >> 5;
    int d = (i < n) ? g_deg[i] : 0;
    if (i < n) g_dinv[i] = rsqrtf((float)(d + 1));
    int x = d;
    #pragma unroll
    for (int o = 1; o < 32; o <<= 1) {
        int y = __shfl_up_sync(0xffffffffu, x, o);
        if (lane >= o) x += y;
    }
    if (lane == 31) wsum[wid] = x;
    __syncthreads();
    if (wid == 0) {
        int w = wsum[lane];
        #pragma unroll
        for (int o = 1; o < 32; o <<= 1) {
            int y = __shfl_up_sync(0xffffffffu, w, o);
            if (lane >= o) w += y;
        }
        wsum[lane] = w;
    }
    __syncthreads();
    int incl = x + (wid > 0 ? wsum[wid - 1] : 0);
    if (i < n) g_off[i + 1] = incl;
    if (threadIdx.x == 1023) g_bsum[blockIdx.x] = incl;
}

__global__ void k_scan2(int nb) {
    __shared__ int ws[4];
    int lane = threadIdx.x & 31, wid = threadIdx.x >> 5;
    int v = (threadIdx.x < nb) ? g_bsum[threadIdx.x] : 0;
    int x = v;
    #pragma unroll
    for (int o = 1; o < 32; o <<= 1) {
        int y = __shfl_up_sync(0xffffffffu, x, o);
        if (lane >= o) x += y;
    }
    if (lane == 31) ws[wid] = x;
    __syncthreads();
    int pre = 0;
    #pragma unroll
    for (int w = 0; w < 4; w++) if (w < wid) pre += ws[w];
    if (threadIdx.x < nb) g_bpref[threadIdx.x] = x - v + pre;
}

__global__ void k_scan3(int n) {
    int i = blockIdx.x * blockDim.x + threadIdx.x;
    if (i == 0) { g_off[0] = 0; g_cur[0] = 0; }
    if (i < n) {
        int v = g_off[i + 1] + g_bpref[i >> 10];
        g_off[i + 1] = v;
        if (i + 1 < n) g_cur[i + 1] = v;
    }
}

__global__ void k_fill(const int* __restrict__ src, const int* __restrict__ dst, int E) {
    int stride = gridDim.x * blockDim.x;
    for (int e = blockIdx.x * blockDim.x + threadIdx.x; e < E; e += stride) {
        int pos = atomicAdd(&g_cur[dst[e]], 1);
        g_csr[pos] = src[e];
    }
}

// ---------------- fp16 mma helper ----------------
__device__ __forceinline__ void mma16h(float c[4], unsigned a0, unsigned a1, unsigned a2,
                                       unsigned a3, unsigned b0, unsigned b1) {
    asm("mma.sync.aligned.m16n8k16.row.col.f32.f16.f16.f32 "
        "{%0,%1,%2,%3}, {%4,%5,%6,%7}, {%8,%9}, {%0,%1,%2,%3};"
        : "+f"(c[0]), "+f"(c[1]), "+f"(c[2]), "+f"(c[3])
        : "r"(a0), "r"(a1), "r"(a2), "r"(a3), "r"(b0), "r"(b1));
}

// ---------------- GEMM1: 3-term fp16, K=256, N=128; half out, NO dinv ----------------
__global__ __launch_bounds__(256)
void gemm1_f16(const float* __restrict__ A, __half* __restrict__ C, int M) {
    constexpr int K = 256, BN = 128, BK = 32;
    constexpr int LDA = 40, LDB = 40;   // halves
    __shared__ __half As_h[128 * LDA], As_l[128 * LDA];
    __shared__ __half Bs_h[BN * LDB],  Bs_l[BN * LDB];

    const int tid  = threadIdx.x;
    const int warp = tid >> 5, lane = tid & 31;
    const int gq   = lane >> 2, tig = lane & 3;
    const int wm   = (warp & 1) * 64;
    const int wn   = (warp >> 1) * 32;
    const int m0   = blockIdx.x * 128;

    float acc[4][4][4];
    #pragma unroll
    for (int mt = 0; mt < 4; mt++)
        #pragma unroll
        for (int nt = 0; nt < 4; nt++)
            #pragma unroll
            for (int q = 0; q < 4; q++) acc[mt][nt][q] = 0.f;

    for (int k0 = 0; k0 < K; k0 += BK) {
        #pragma unroll
        for (int it = 0; it < 4; it++) {          // A: 128x32 floats -> hi/lo halves
            int idx = it * 256 + tid;
            int r = idx >> 3, c = (idx & 7) * 4;
            int gm = m0 + r;
            float4 v = make_float4(0.f, 0.f, 0.f, 0.f);
            if (gm < M) v = *(const float4*)&A[(size_t)gm * K + k0 + c];
            __half hx = __float2half_rn(v.x), hy = __float2half_rn(v.y);
            __half hz = __float2half_rn(v.z), hw = __float2half_rn(v.w);
            *(__half2*)&As_h[r * LDA + c]     = __halves2half2(hx, hy);
            *(__half2*)&As_h[r * LDA + c + 2] = __halves2half2(hz, hw);
            *(__half2*)&As_l[r * LDA + c] = __halves2half2(
                __float2half_rn(v.x - __half2float(hx)), __float2half_rn(v.y - __half2float(hy)));
            *(__half2*)&As_l[r * LDA + c + 2] = __halves2half2(
                __float2half_rn(v.z - __half2float(hz)), __float2half_rn(v.w - __half2float(hw)));
        }
        #pragma unroll
        for (int it = 0; it < 2; it++) {          // B: [128n][32k] halves, pre-split
            int idx = it * 256 + tid;
            int n = idx >> 2, c = (idx & 3) * 8;
            *(uint4*)&Bs_h[n * LDB + c] = *(const uint4*)&g_W1th[n * 256 + k0 + c];
            *(uint4*)&Bs_l[n * LDB + c] = *(const uint4*)&g_W1tl[n * 256 + k0 + c];
        }
        __syncthreads();
        #pragma unroll
        for (int ks = 0; ks < 2; ks++) {
            const int kb = ks * 16;
            unsigned bh[4][2], bl[4][2];
            #pragma unroll
            for (int nt = 0; nt < 4; nt++) {
                int col = wn + nt * 8 + gq;
                bh[nt][0] = *(const unsigned*)&Bs_h[col * LDB + kb + 2 * tig];
                bh[nt][1] = *(const unsigned*)&Bs_h[col * LDB + kb + 2 * tig + 8];
                bl[nt][0] = *(const unsigned*)&Bs_l[col * LDB + kb + 2 * tig];
                bl[nt][1] = *(const unsigned*)&Bs_l[col * LDB + kb + 2 * tig + 8];
            }
            #pragma unroll
            for (int mt = 0; mt < 4; mt++) {
                int row = wm + mt * 16 + gq;
                unsigned ah0 = *(const unsigned*)&As_h[row * LDA + kb + 2 * tig];
                unsigned ah1 = *(const unsigned*)&As_h[(row + 8) * LDA + kb + 2 * tig];
                unsigned ah2 = *(const unsigned*)&As_h[row * LDA + kb + 2 * tig + 8];
                unsigned ah3 = *(const unsigned*)&As_h[(row + 8) * LDA + kb + 2 * tig + 8];
                unsigned al0 = *(const unsigned*)&As_l[row * LDA + kb + 2 * tig];
                unsigned al1 = *(const unsigned*)&As_l[(row + 8) * LDA + kb + 2 * tig];
                unsigned al2 = *(const unsigned*)&As_l[row * LDA + kb + 2 * tig + 8];
                unsigned al3 = *(const unsigned*)&As_l[(row + 8) * LDA + kb + 2 * tig + 8];
                #pragma unroll
                for (int nt = 0; nt < 4; nt++) {
                    mma16h(acc[mt][nt], ah0, ah1, ah2, ah3, bh[nt][0], bh[nt][1]);
                    mma16h(acc[mt][nt], al0, al1, al2, al3, bh[nt][0], bh[nt][1]);
                    mma16h(acc[mt][nt], ah0, ah1, ah2, ah3, bl[nt][0], bl[nt][1]);
                }
            }
        }
        __syncthreads();
    }

    #pragma unroll
    for (int mt = 0; mt < 4; mt++) {
        int r0 = m0 + wm + mt * 16 + gq;
        int r1 = r0 + 8;
        #pragma unroll
        for (int nt = 0; nt < 4; nt++) {
            int col = wn + nt * 8 + 2 * tig;
            if (r0 < M)
                *(__half2*)&C[(size_t)r0 * BN + col] = __floats2half2_rn(acc[mt][nt][0], acc[mt][nt][1]);
            if (r1 < M)
                *(__half2*)&C[(size_t)r1 * BN + col] = __floats2half2_rn(acc[mt][nt][2], acc[mt][nt][3]);
        }
    }
}

// ---------------- GEMM2: 2-term fp16 (A=h1 half, W2 hi/lo), K=128, N=64, dinv epi ----------------
__global__ __launch_bounds__(256)
void gemm2_f16(const __half* __restrict__ A, __half* __restrict__ C, int M) {
    constexpr int K = 128, BN = 64, BK = 64;
    constexpr int LDA = 72, LDB = 72;   // halves
    __shared__ __half As[128 * LDA];
    __shared__ __half Bth[BN * LDB], Btl[BN * LDB];

    const int tid  = threadIdx.x;
    const int warp = tid >> 5, lane = tid & 31;
    const int gq   = lane >> 2, tig = lane & 3;
    const int wm   = (warp & 1) * 64;
    const int wn   = (warp >> 1) * 16;
    const int m0   = blockIdx.x * 128;

    float acc[4][2][4];
    #pragma unroll
    for (int mt = 0; mt < 4; mt++)
        #pragma unroll
        for (int nt = 0; nt < 2; nt++)
            #pragma unroll
            for (int q = 0; q < 4; q++) acc[mt][nt][q] = 0.f;

    for (int k0 = 0; k0 < K; k0 += BK) {
        #pragma unroll
        for (int it = 0; it < 4; it++) {          // A: 128x64 halves
            int idx = it * 256 + tid;
            int r = idx >> 3, c = (idx & 7) * 8;
            int gm = m0 + r;
            uint4 v = make_uint4(0u, 0u, 0u, 0u);
            if (gm < M) v = *(const uint4*)&A[(size_t)gm * K + k0 + c];
            *(uint4*)&As[r * LDA + c] = v;
        }
        #pragma unroll
        for (int it = 0; it < 2; it++) {          // B: [64n][64k] halves, pre-split
            int idx = it * 256 + tid;
            int n = idx >> 3, c = (idx & 7) * 8;
            *(uint4*)&Bth[n * LDB + c] = *(const uint4*)&g_W2th[n * 128 + k0 + c];
            *(uint4*)&Btl[n * LDB + c] = *(const uint4*)&g_W2tl[n * 128 + k0 + c];
        }
        __syncthreads();
        #pragma unroll
        for (int ks = 0; ks < 4; ks++) {
            const int kb = ks * 16;
            unsigned bh[2][2], bl[2][2];
            #pragma unroll
            for (int nt = 0; nt < 2; nt++) {
                int col = wn + nt * 8 + gq;
                bh[nt][0] = *(const unsigned*)&Bth[col * LDB + kb + 2 * tig];
                bh[nt][1] = *(const unsigned*)&Bth[col * LDB + kb + 2 * tig + 8];
                bl[nt][0] = *(const unsigned*)&Btl[col * LDB + kb + 2 * tig];
                bl[nt][1] = *(const unsigned*)&Btl[col * LDB + kb + 2 * tig + 8];
            }
            #pragma unroll
            for (int mt = 0; mt < 4; mt++) {
                int row = wm + mt * 16 + gq;
                unsigned a0 = *(const unsigned*)&As[row * LDA + kb + 2 * tig];
                unsigned a1 = *(const unsigned*)&As[(row + 8) * LDA + kb + 2 * tig];
                unsigned a2 = *(const unsigned*)&As[row * LDA + kb + 2 * tig + 8];
                unsigned a3 = *(const unsigned*)&As[(row + 8) * LDA + kb + 2 * tig + 8];
                #pragma unroll
                for (int nt = 0; nt < 2; nt++) {
                    mma16h(acc[mt][nt], a0, a1, a2, a3, bh[nt][0], bh[nt][1]);
                    mma16h(acc[mt][nt], a0, a1, a2, a3, bl[nt][0], bl[nt][1]);
                }
            }
        }
        __syncthreads();
    }

    #pragma unroll
    for (int mt = 0; mt < 4; mt++) {
        int r0 = m0 + wm + mt * 16 + gq;
        int r1 = r0 + 8;
        #pragma unroll
        for (int nt = 0; nt < 2; nt++) {
            int col = wn + nt * 8 + 2 * tig;
            if (r0 < M) {
                float s = g_dinv[r0];
                *(__half2*)&C[(size_t)r0 * BN + col] =
                    __floats2half2_rn(acc[mt][nt][0] * s, acc[mt][nt][1] * s);
            }
            if (r1 < M) {
                float s = g_dinv[r1];
                *(__half2*)&C[(size_t)r1 * BN + col] =
                    __floats2half2_rn(acc[mt][nt][2] * s, acc[mt][nt][3] * s);
            }
        }
    }
}

// ---------------- aggregation (warp per node; dinv[src] applied here) ----------------
__global__ __launch_bounds__(256)
void k_agg1(const float* __restrict__ b1, int N) {
    int d = blockIdx.x * 8 + (threadIdx.x >> 5);
    if (d >= N) return;
    int l = threadIdx.x & 31;
    const uint2* y = (const uint2*)g_buf1;       // half[.][128]
    float dd = g_dinv[d];
    uint2 u = y[(size_t)d * 32 + l];
    float2 f0 = __half22float2(*(__half2*)&u.x);
    float2 f1 = __half22float2(*(__half2*)&u.y);
    float a0 = f0.x * dd, a1 = f0.y * dd, a2 = f1.x * dd, a3 = f1.y * dd;
    int e = g_off[d], e1 = g_off[d + 1];
    for (; e + 4 <= e1; e += 4) {
        int s0 = g_csr[e], s1 = g_csr[e + 1], s2 = g_csr[e + 2], s3 = g_csr[e + 3];
        float d0 = g_dinv[s0], d1 = g_dinv[s1], d2 = g_dinv[s2], d3 = g_dinv[s3];
        uint2 u0 = y[(size_t)s0 * 32 + l];
        uint2 u1 = y[(size_t)s1 * 32 + l];
        uint2 u2 = y[(size_t)s2 * 32 + l];
        uint2 u3 = y[(size_t)s3 * 32 + l];
        float2 p;
        p = __half22float2(*(__half2*)&u0.x); a0 = fmaf(p.x, d0, a0); a1 = fmaf(p.y, d0, a1);
        p = __half22float2(*(__half2*)&u0.y); a2 = fmaf(p.x, d0, a2); a3 = fmaf(p.y, d0, a3);
        p = __half22float2(*(__half2*)&u1.x); a0 = fmaf(p.x, d1, a0); a1 = fmaf(p.y, d1, a1);
        p = __half22float2(*(__half2*)&u1.y); a2 = fmaf(p.x, d1, a2); a3 = fmaf(p.y, d1, a3);
        p = __half22float2(*(__half2*)&u2.x); a0 = fmaf(p.x, d2, a0); a1 = fmaf(p.y, d2, a1);
        p = __half22float2(*(__half2*)&u2.y); a2 = fmaf(p.x, d2, a2); a3 = fmaf(p.y, d2, a3);
        p = __half22float2(*(__half2*)&u3.x); a0 = fmaf(p.x, d3, a0); a1 = fmaf(p.y, d3, a1);
        p = __half22float2(*(__half2*)&u3.y); a2 = fmaf(p.x, d3, a2); a3 = fmaf(p.y, d3, a3);
    }
    for (; e < e1; e++) {
        int s0 = g_csr[e];
        float d0 = g_dinv[s0];
        uint2 u0 = y[(size_t)s0 * 32 + l];
        float2 p;
        p = __half22float2(*(__half2*)&u0.x); a0 = fmaf(p.x, d0, a0); a1 = fmaf(p.y, d0, a1);
        p = __half22float2(*(__half2*)&u0.y); a2 = fmaf(p.x, d0, a2); a3 = fmaf(p.y, d0, a3);
    }
    const float4 b = ((const float4*)b1)[l];
    uint2 o;
    *(__half2*)&o.x = __floats2half2_rn(fmaxf(a0 * dd + b.x, 0.f), fmaxf(a1 * dd + b.y, 0.f));
    *(__half2*)&o.y = __floats2half2_rn(fmaxf(a2 * dd + b.z, 0.f), fmaxf(a3 * dd + b.w, 0.f));
    ((uint2*)g_buf2)[(size_t)d * 32 + l] = o;
}

__global__ __launch_bounds__(256)
void k_agg2(const float* __restrict__ b2, int N) {
    int d = blockIdx.x * 8 + (threadIdx.x >> 5);
    if (d >= N) return;
    int l = threadIdx.x & 31;
    const __half2* y = (const __half2*)g_buf3;   // half[.][64]
    float2 acc = __half22float2(y[(size_t)d * 32 + l]);
    int e = g_off[d], e1 = g_off[d + 1];
    for (; e + 4 <= e1; e += 4) {
        int s0 = g_csr[e], s1 = g_csr[e + 1], s2 = g_csr[e + 2], s3 = g_csr[e + 3];
        float2 v0 = __half22float2(y[(size_t)s0 * 32 + l]);
        float2 v1 = __half22float2(y[(size_t)s1 * 32 + l]);
        float2 v2 = __half22float2(y[(size_t)s2 * 32 + l]);
        float2 v3 = __half22float2(y[(size_t)s3 * 32 + l]);
        acc.x += v0.x + v1.x + v2.x + v3.x;
        acc.y += v0.y + v1.y + v2.y + v3.y;
    }
    for (; e < e1; e++) {
        float2 v = __half22float2(y[(size_t)g_csr[e] * 32 + l]);
        acc.x += v.x; acc.y += v.y;
    }
    float s = g_dinv[d];
    const float2 b = ((const float2*)b2)[l];
    ((float2*)g_buf1)[(size_t)d * 32 + l] = make_float2(acc.x * s + b.x, acc.y * s + b.y);
}

// ---------------- fused head ----------------
__global__ __launch_bounds__(256)
void k_head(const int* __restrict__ batch, const float* __restrict__ fcW,
            const float* __restrict__ fcb, float* __restrict__ out, int N) {
    __shared__ int s_lo, s_hi;
    __shared__ float s_red[256];
    __shared__ float s_mean[64];
    __shared__ float s_logit[4];
    const int gph = blockIdx.x;
    const int tid = threadIdx.x;
    if (tid == 0) {
        int lo = 0, hi = N;
        while (lo < hi) { int m = (lo + hi) >> 1; if (batch[m] < gph) lo = m + 1; else hi = m; }
        s_lo = lo;
        int lo2 = lo, hi2 = N;
        while (lo2 < hi2) { int m = (lo2 + hi2) >> 1; if (batch[m] < gph + 1) lo2 = m + 1; else hi2 = m; }
        s_hi = lo2;
    }
    __syncthreads();
    const int lo = s_lo, hi = s_hi;
    const float inv = 1.f / fmaxf((float)(hi - lo), 1.f);
    const int f = tid & 63, sub = tid >> 6;
    const float* h2 = g_buf1;
    float sum = 0.f;
    for (int i = lo + sub; i < hi; i += 4) sum += h2[(size_t)i * 64 + f];
    s_red[tid] = sum;
    __syncthreads();
    if (tid < 64) {
        float t = s_red[tid] + s_red[tid + 64] + s_red[tid + 128] + s_red[tid + 192];
        s_mean[tid] = t * inv;
    }
    __syncthreads();
    if (tid < 4) {
        float l = fcb[tid];
        #pragma unroll 8
        for (int k = 0; k < 64; k++) l += s_mean[k] * fcW[k * 4 + tid];
        s_logit[tid] = l;
    }
    __syncthreads();
    if (tid == 0) {
        float l0 = s_logit[0], l1 = s_logit[1], l2 = s_logit[2], l3 = s_logit[3];
        float m = fmaxf(fmaxf(l0, l1), fmaxf(l2, l3));
        float s = expf(l0 - m) + expf(l1 - m) + expf(l2 - m) + expf(l3 - m);
        float ls = m + logf(s);
        out[gph * 4 + 0] = l0 - ls;
        out[gph * 4 + 1] = l1 - ls;
        out[gph * 4 + 2] = l2 - ls;
        out[gph * 4 + 3] = l3 - ls;
    }
}

// ---------------- launch (forked capture stream: GEMM1 || CSR build) ----------------
extern "C" void kernel_launch(void* const* d_in, const int* in_sizes, int n_in,
                              void* d_out, int out_size) {
    const float* x     = (const float*)d_in[0];
    const int*   ei    = (const int*)d_in[1];
    const int*   batch = (const int*)d_in[2];
    const float* W1    = (const float*)d_in[3];
    const float* b1    = (const float*)d_in[4];
    const float* W2    = (const float*)d_in[5];
    const float* b2    = (const float*)d_in[6];
    const float* fcW   = (const float*)d_in[7];
    const float* fcb   = (const float*)d_in[8];
    float* out = (float*)d_out;

    const int N = in_sizes[0] / 256;
    const int E = in_sizes[1] / 2;
    const int G = out_size / 4;
    const int* src = ei;
    const int* dst = ei + E;

    static cudaStream_t s2 = [] {
        cudaStream_t s; cudaStreamCreateWithFlags(&s, cudaStreamNonBlocking); return s;
    }();
    static cudaEvent_t ev1 = [] {
        cudaEvent_t e; cudaEventCreateWithFlags(&e, cudaEventDisableTiming); return e;
    }();
    static cudaEvent_t ev2 = [] {
        cudaEvent_t e; cudaEventCreateWithFlags(&e, cudaEventDisableTiming); return e;
    }();

    float *b1p, *b2p, *b3p;
    int *degp;
    cudaGetSymbolAddress((void**)&b1p, g_buf1);
    cudaGetSymbolAddress((void**)&b2p, g_buf2);
    cudaGetSymbolAddress((void**)&b3p, g_buf3);
    cudaGetSymbolAddress((void**)&degp, g_deg);
    __half* y1h = (__half*)b1p;
    __half* h1h = (__half*)b2p;
    __half* y2h = (__half*)b3p;

    const int nb    = (N + 255) / 256;
    const int nscan = (N + 1023) / 1024;
    const int gm    = (N + 127) / 128;
    const int ga    = (N + 7) / 8;

    // fork: tensor branch (weights convert + GEMM1) on s2
    cudaEventRecord(ev1, 0);
    cudaStreamWaitEvent(s2, ev1, 0);
    k_wconv<<<160, 256, 0, s2>>>(W1, W2);
    gemm1_f16<<<gm, 256, 0, s2>>>(x, y1h, N);
    cudaEventRecord(ev2, s2);

    // prep branch (CSR build) on main stream
    cudaMemsetAsync(degp, 0, (size_t)N * sizeof(int), 0);
    k_count<<<1184, 256>>>(dst, E);
    k_scan1<<<nscan, 1024>>>(N);
    k_scan2<<<1, 128>>>(nscan);
    k_scan3<<<nb, 256>>>(N);
    k_fill<<<1184, 256>>>(src, dst, E);

    // join, then serial tail
    cudaStreamWaitEvent(0, ev2, 0);
    k_agg1<<<ga, 256>>>(b1, N);
    gemm2_f16<<<gm, 256>>>(h1h, y2h, N);
    k_agg2<<<ga, 256>>>(b2, N);
    k_head<<<G, 256>>>(batch, fcW, fcb, out, N);
}

// round 7
// speedup vs baseline: 2.2009x; 1.1893x over previous
#include <cuda_runtime.h>
#include <cuda_fp16.h>

#define NNODES_MAX 100000
#define NEDGES_MAX 1600000
#define NG_MAX     1000

// ---------------- scratch (static device globals; no allocation) ----------------
__device__ int   g_deg[NNODES_MAX];
__device__ float g_dinv[NNODES_MAX];
__device__ int   g_off[NNODES_MAX + 1];
__device__ int   g_cur[NNODES_MAX];
__device__ int   g_csr[NEDGES_MAX];
__device__ int   g_bsum[256];
__device__ int   g_bpref[256];
// g_buf1: y1 as half [N][128] (gemm1 out, unscaled), later h2 as half [N][64]
// g_buf2: h1 as half [N][128]
// g_buf3: y2 as half [N][64]
__device__ __align__(16) float g_buf1[NNODES_MAX * 128];
__device__ __align__(16) float g_buf2[NNODES_MAX * 64];
__device__ __align__(16) float g_buf3[NNODES_MAX * 32];
// pre-split transposed weights: [n][k] half hi/lo
__device__ __align__(16) __half g_W1th[128 * 256], g_W1tl[128 * 256];
__device__ __align__(16) __half g_W2th[64 * 128],  g_W2tl[64 * 128];

// ---------------- weight convert (hi/lo split + transpose) ----------------
__global__ void k_wconv(const float* __restrict__ W1, const float* __restrict__ W2) {
    int i = blockIdx.x * blockDim.x + threadIdx.x;
    if (i < 256 * 128) {
        int k = i >> 7, n = i & 127;
        float v = W1[i];
        __half h = __float2half_rn(v);
        g_W1th[n * 256 + k] = h;
        g_W1tl[n * 256 + k] = __float2half_rn(v - __half2float(h));
    } else if (i < 256 * 128 + 128 * 64) {
        int j = i - 256 * 128;
        int k = j >> 6, n = j & 63;
        float v = W2[j];
        __half h = __float2half_rn(v);
        g_W2th[n * 128 + k] = h;
        g_W2tl[n * 128 + k] = __float2half_rn(v - __half2float(h));
    }
}

// ---------------- degree / scan / CSR ----------------
__global__ void k_count(const int* __restrict__ dst, int E) {
    int stride = gridDim.x * blockDim.x;
    for (int i = blockIdx.x * blockDim.x + threadIdx.x; i < E; i += stride)
        atomicAdd(&g_deg[dst[i]], 1);
}

__global__ void k_scan1(int n) {
    __shared__ int wsum[32];
    int i = blockIdx.x * 1024 + threadIdx.x;
    int lane = threadIdx.x & 31, wid = threadIdx.x >> 5;
    int d = (i < n) ? g_deg[i] : 0;
    if (i < n) g_dinv[i] = rsqrtf((float)(d + 1));
    int x = d;
    #pragma unroll
    for (int o = 1; o < 32; o <<= 1) {
        int y = __shfl_up_sync(0xffffffffu, x, o);
        if (lane >= o) x += y;
    }
    if (lane == 31) wsum[wid] = x;
    __syncthreads();
    if (wid == 0) {
        int w = wsum[lane];
        #pragma unroll
        for (int o = 1; o < 32; o <<= 1) {
            int y = __shfl_up_sync(0xffffffffu, w, o);
            if (lane >= o) w += y;
        }
        wsum[lane] = w;
    }
    __syncthreads();
    int incl = x + (wid > 0 ? wsum[wid - 1] : 0);
    if (i < n) g_off[i + 1] = incl;
    if (threadIdx.x == 1023) g_bsum[blockIdx.x] = incl;
}

__global__ void k_scan2(int nb) {
    __shared__ int ws[4];
    int lane = threadIdx.x & 31, wid = threadIdx.x >> 5;
    int v = (threadIdx.x < nb) ? g_bsum[threadIdx.x] : 0;
    int x = v;
    #pragma unroll
    for (int o = 1; o < 32; o <<= 1) {
        int y = __shfl_up_sync(0xffffffffu, x, o);
        if (lane >= o) x += y;
    }
    if (lane == 31) ws[wid] = x;
    __syncthreads();
    int pre = 0;
    #pragma unroll
    for (int w = 0; w < 4; w++) if (w < wid) pre += ws[w];
    if (threadIdx.x < nb) g_bpref[threadIdx.x] = x - v + pre;
}

__global__ void k_scan3(int n) {
    int i = blockIdx.x * blockDim.x + threadIdx.x;
    if (i == 0) { g_off[0] = 0; g_cur[0] = 0; }
    if (i < n) {
        int v = g_off[i + 1] + g_bpref[i >> 10];
        g_off[i + 1] = v;
        if (i + 1 < n) g_cur[i + 1] = v;
    }
}

__global__ void k_fill(const int* __restrict__ src, const int* __restrict__ dst, int E) {
    int stride = gridDim.x * blockDim.x;
    for (int e = blockIdx.x * blockDim.x + threadIdx.x; e < E; e += stride) {
        int pos = atomicAdd(&g_cur[dst[e]], 1);
        g_csr[pos] = src[e];
    }
}

// ---------------- mma / ldmatrix helpers ----------------
__device__ __forceinline__ void mma16h(float c[4], unsigned a0, unsigned a1, unsigned a2,
                                       unsigned a3, unsigned b0, unsigned b1) {
    asm("mma.sync.aligned.m16n8k16.row.col.f32.f16.f16.f32 "
        "{%0,%1,%2,%3}, {%4,%5,%6,%7}, {%8,%9}, {%0,%1,%2,%3};"
        : "+f"(c[0]), "+f"(c[1]), "+f"(c[2]), "+f"(c[3])
        : "r"(a0), "r"(a1), "r"(a2), "r"(a3), "r"(b0), "r"(b1));
}

__device__ __forceinline__ void ldsm4(unsigned& r0, unsigned& r1, unsigned& r2,
                                      unsigned& r3, unsigned addr) {
    asm volatile("ldmatrix.sync.aligned.m8n8.x4.shared.b16 {%0,%1,%2,%3}, [%4];"
                 : "=r"(r0), "=r"(r1), "=r"(r2), "=r"(r3) : "r"(addr));
}

__device__ __forceinline__ void ldsm2(unsigned& r0, unsigned& r1, unsigned addr) {
    asm volatile("ldmatrix.sync.aligned.m8n8.x2.shared.b16 {%0,%1}, [%2];"
                 : "=r"(r0), "=r"(r1) : "r"(addr));
}

// ---------------- GEMM1: 2-term fp16 (A rounded, W1 hi/lo), K=256, N=128 ----------------
// y1[m][n] = sum_k x[m][k]*W1[k][n]   (half out, NO dinv — applied in agg1)
__global__ __launch_bounds__(256)
void gemm1_f16(const float* __restrict__ A, __half* __restrict__ C, int M) {
    constexpr int K = 256, BN = 128, BK = 32;
    constexpr int LDA = 40, LDB = 40;   // halves; rows 80B apart -> ldmatrix conflict-free
    __shared__ __half As_h[128 * LDA];
    __shared__ __half Bs_h[BN * LDB], Bs_l[BN * LDB];

    const int tid  = threadIdx.x;
    const int warp = tid >> 5, lane = tid & 31;
    const int gq   = lane >> 2, tig = lane & 3;
    const int wm   = (warp & 1) * 64;
    const int wn   = (warp >> 1) * 32;
    const int m0   = blockIdx.x * 128;

    // ldmatrix lane-address templates (bytes)
    const unsigned sA  = (unsigned)__cvta_generic_to_shared(As_h);
    const unsigned sBh = (unsigned)__cvta_generic_to_shared(Bs_h);
    const unsigned sBl = (unsigned)__cvta_generic_to_shared(Bs_l);
    const int aLaneOff = ((lane & 15) * LDA + (lane >> 4) * 8) * 2;
    const int bl15 = lane & 15;
    const int bLaneOff = ((bl15 & 7) * LDB + (bl15 >> 3) * 8) * 2;
    unsigned aBase[4], bBaseH[4], bBaseL[4];
    #pragma unroll
    for (int mt = 0; mt < 4; mt++)
        aBase[mt] = sA + (wm + mt * 16) * LDA * 2 + aLaneOff;
    #pragma unroll
    for (int nt = 0; nt < 4; nt++) {
        bBaseH[nt] = sBh + (wn + nt * 8) * LDB * 2 + bLaneOff;
        bBaseL[nt] = sBl + (wn + nt * 8) * LDB * 2 + bLaneOff;
    }

    float acc[4][4][4];
    #pragma unroll
    for (int mt = 0; mt < 4; mt++)
        #pragma unroll
        for (int nt = 0; nt < 4; nt++)
            #pragma unroll
            for (int q = 0; q < 4; q++) acc[mt][nt][q] = 0.f;

    for (int k0 = 0; k0 < K; k0 += BK) {
        #pragma unroll
        for (int it = 0; it < 4; it++) {          // A: 128x32 floats -> rounded halves
            int idx = it * 256 + tid;
            int r = idx >> 3, c = (idx & 7) * 4;
            int gm = m0 + r;
            float4 v = make_float4(0.f, 0.f, 0.f, 0.f);
            if (gm < M) v = *(const float4*)&A[(size_t)gm * K + k0 + c];
            uint2 p;
            *(__half2*)&p.x = __floats2half2_rn(v.x, v.y);
            *(__half2*)&p.y = __floats2half2_rn(v.z, v.w);
            *(uint2*)&As_h[r * LDA + c] = p;
        }
        #pragma unroll
        for (int it = 0; it < 2; it++) {          // B: [128n][32k] halves, pre-split
            int idx = it * 256 + tid;
            int n = idx >> 2, c = (idx & 3) * 8;
            *(uint4*)&Bs_h[n * LDB + c] = *(const uint4*)&g_W1th[n * 256 + k0 + c];
            *(uint4*)&Bs_l[n * LDB + c] = *(const uint4*)&g_W1tl[n * 256 + k0 + c];
        }
        __syncthreads();
        #pragma unroll
        for (int ks = 0; ks < 2; ks++) {
            const int kbB = ks * 16 * 2;          // byte offset
            unsigned bh[4][2], bl[4][2];
            #pragma unroll
            for (int nt = 0; nt < 4; nt++) {
                ldsm2(bh[nt][0], bh[nt][1], bBaseH[nt] + kbB);
                ldsm2(bl[nt][0], bl[nt][1], bBaseL[nt] + kbB);
            }
            #pragma unroll
            for (int mt = 0; mt < 4; mt++) {
                unsigned a0, a1, a2, a3;
                ldsm4(a0, a1, a2, a3, aBase[mt] + kbB);
                #pragma unroll
                for (int nt = 0; nt < 4; nt++) {
                    mma16h(acc[mt][nt], a0, a1, a2, a3, bh[nt][0], bh[nt][1]);
                    mma16h(acc[mt][nt], a0, a1, a2, a3, bl[nt][0], bl[nt][1]);
                }
            }
        }
        __syncthreads();
    }

    #pragma unroll
    for (int mt = 0; mt < 4; mt++) {
        int r0 = m0 + wm + mt * 16 + gq;
        int r1 = r0 + 8;
        #pragma unroll
        for (int nt = 0; nt < 4; nt++) {
            int col = wn + nt * 8 + 2 * tig;
            if (r0 < M)
                *(__half2*)&C[(size_t)r0 * BN + col] = __floats2half2_rn(acc[mt][nt][0], acc[mt][nt][1]);
            if (r1 < M)
                *(__half2*)&C[(size_t)r1 * BN + col] = __floats2half2_rn(acc[mt][nt][2], acc[mt][nt][3]);
        }
    }
}

// ---------------- GEMM2: 2-term fp16 (A=h1 half, W2 hi/lo), K=128, N=64, dinv epi ----------------
__global__ __launch_bounds__(256)
void gemm2_f16(const __half* __restrict__ A, __half* __restrict__ C, int M) {
    constexpr int K = 128, BN = 64, BK = 64;
    constexpr int LDA = 72, LDB = 72;   // halves
    __shared__ __half As[128 * LDA];
    __shared__ __half Bth[BN * LDB], Btl[BN * LDB];

    const int tid  = threadIdx.x;
    const int warp = tid >> 5, lane = tid & 31;
    const int gq   = lane >> 2, tig = lane & 3;
    const int wm   = (warp & 1) * 64;
    const int wn   = (warp >> 1) * 16;
    const int m0   = blockIdx.x * 128;

    float acc[4][2][4];
    #pragma unroll
    for (int mt = 0; mt < 4; mt++)
        #pragma unroll
        for (int nt = 0; nt < 2; nt++)
            #pragma unroll
            for (int q = 0; q < 4; q++) acc[mt][nt][q] = 0.f;

    for (int k0 = 0; k0 < K; k0 += BK) {
        #pragma unroll
        for (int it = 0; it < 4; it++) {          // A: 128x64 halves
            int idx = it * 256 + tid;
            int r = idx >> 3, c = (idx & 7) * 8;
            int gm = m0 + r;
            uint4 v = make_uint4(0u, 0u, 0u, 0u);
            if (gm < M) v = *(const uint4*)&A[(size_t)gm * K + k0 + c];
            *(uint4*)&As[r * LDA + c] = v;
        }
        #pragma unroll
        for (int it = 0; it < 2; it++) {          // B: [64n][64k] halves, pre-split
            int idx = it * 256 + tid;
            int n = idx >> 3, c = (idx & 7) * 8;
            *(uint4*)&Bth[n * LDB + c] = *(const uint4*)&g_W2th[n * 128 + k0 + c];
            *(uint4*)&Btl[n * LDB + c] = *(const uint4*)&g_W2tl[n * 128 + k0 + c];
        }
        __syncthreads();
        #pragma unroll
        for (int ks = 0; ks < 4; ks++) {
            const int kb = ks * 16;
            unsigned bh[2][2], bl[2][2];
            #pragma unroll
            for (int nt = 0; nt < 2; nt++) {
                int col = wn + nt * 8 + gq;
                bh[nt][0] = *(const unsigned*)&Bth[col * LDB + kb + 2 * tig];
                bh[nt][1] = *(const unsigned*)&Bth[col * LDB + kb + 2 * tig + 8];
                bl[nt][0] = *(const unsigned*)&Btl[col * LDB + kb + 2 * tig];
                bl[nt][1] = *(const unsigned*)&Btl[col * LDB + kb + 2 * tig + 8];
            }
            #pragma unroll
            for (int mt = 0; mt < 4; mt++) {
                int row = wm + mt * 16 + gq;
                unsigned a0 = *(const unsigned*)&As[row * LDA + kb + 2 * tig];
                unsigned a1 = *(const unsigned*)&As[(row + 8) * LDA + kb + 2 * tig];
                unsigned a2 = *(const unsigned*)&As[row * LDA + kb + 2 * tig + 8];
                unsigned a3 = *(const unsigned*)&As[(row + 8) * LDA + kb + 2 * tig + 8];
                #pragma unroll
                for (int nt = 0; nt < 2; nt++) {
                    mma16h(acc[mt][nt], a0, a1, a2, a3, bh[nt][0], bh[nt][1]);
                    mma16h(acc[mt][nt], a0, a1, a2, a3, bl[nt][0], bl[nt][1]);
                }
            }
        }
        __syncthreads();
    }

    #pragma unroll
    for (int mt = 0; mt < 4; mt++) {
        int r0 = m0 + wm + mt * 16 + gq;
        int r1 = r0 + 8;
        #pragma unroll
        for (int nt = 0; nt < 2; nt++) {
            int col = wn + nt * 8 + 2 * tig;
            if (r0 < M) {
                float s = g_dinv[r0];
                *(__half2*)&C[(size_t)r0 * BN + col] =
                    __floats2half2_rn(acc[mt][nt][0] * s, acc[mt][nt][1] * s);
            }
            if (r1 < M) {
                float s = g_dinv[r1];
                *(__half2*)&C[(size_t)r1 * BN + col] =
                    __floats2half2_rn(acc[mt][nt][2] * s, acc[mt][nt][3] * s);
            }
        }
    }
}

// ---------------- aggregation (warp per node; dinv[src] applied here) ----------------
__global__ __launch_bounds__(256)
void k_agg1(const float* __restrict__ b1, int N) {
    int d = blockIdx.x * 8 + (threadIdx.x >> 5);
    if (d >= N) return;
    int l = threadIdx.x & 31;
    const uint2* y = (const uint2*)g_buf1;       // half[.][128]
    float dd = g_dinv[d];
    uint2 u = y[(size_t)d * 32 + l];
    float2 f0 = __half22float2(*(__half2*)&u.x);
    float2 f1 = __half22float2(*(__half2*)&u.y);
    float a0 = f0.x * dd, a1 = f0.y * dd, a2 = f1.x * dd, a3 = f1.y * dd;
    int e = g_off[d], e1 = g_off[d + 1];
    for (; e + 4 <= e1; e += 4) {
        int s0 = g_csr[e], s1 = g_csr[e + 1], s2 = g_csr[e + 2], s3 = g_csr[e + 3];
        float d0 = g_dinv[s0], d1 = g_dinv[s1], d2 = g_dinv[s2], d3 = g_dinv[s3];
        uint2 u0 = y[(size_t)s0 * 32 + l];
        uint2 u1 = y[(size_t)s1 * 32 + l];
        uint2 u2 = y[(size_t)s2 * 32 + l];
        uint2 u3 = y[(size_t)s3 * 32 + l];
        float2 p;
        p = __half22float2(*(__half2*)&u0.x); a0 = fmaf(p.x, d0, a0); a1 = fmaf(p.y, d0, a1);
        p = __half22float2(*(__half2*)&u0.y); a2 = fmaf(p.x, d0, a2); a3 = fmaf(p.y, d0, a3);
        p = __half22float2(*(__half2*)&u1.x); a0 = fmaf(p.x, d1, a0); a1 = fmaf(p.y, d1, a1);
        p = __half22float2(*(__half2*)&u1.y); a2 = fmaf(p.x, d1, a2); a3 = fmaf(p.y, d1, a3);
        p = __half22float2(*(__half2*)&u2.x); a0 = fmaf(p.x, d2, a0); a1 = fmaf(p.y, d2, a1);
        p = __half22float2(*(__half2*)&u2.y); a2 = fmaf(p.x, d2, a2); a3 = fmaf(p.y, d2, a3);
        p = __half22float2(*(__half2*)&u3.x); a0 = fmaf(p.x, d3, a0); a1 = fmaf(p.y, d3, a1);
        p = __half22float2(*(__half2*)&u3.y); a2 = fmaf(p.x, d3, a2); a3 = fmaf(p.y, d3, a3);
    }
    for (; e < e1; e++) {
        int s0 = g_csr[e];
        float d0 = g_dinv[s0];
        uint2 u0 = y[(size_t)s0 * 32 + l];
        float2 p;
        p = __half22float2(*(__half2*)&u0.x); a0 = fmaf(p.x, d0, a0); a1 = fmaf(p.y, d0, a1);
        p = __half22float2(*(__half2*)&u0.y); a2 = fmaf(p.x, d0, a2); a3 = fmaf(p.y, d0, a3);
    }
    const float4 b = ((const float4*)b1)[l];
    uint2 o;
    *(__half2*)&o.x = __floats2half2_rn(fmaxf(a0 * dd + b.x, 0.f), fmaxf(a1 * dd + b.y, 0.f));
    *(__half2*)&o.y = __floats2half2_rn(fmaxf(a2 * dd + b.z, 0.f), fmaxf(a3 * dd + b.w, 0.f));
    ((uint2*)g_buf2)[(size_t)d * 32 + l] = o;
}

// h2 (half, into g_buf1) = dinv[d]*(y2[d] + sum y2[s]) + b2
__global__ __launch_bounds__(256)
void k_agg2(const float* __restrict__ b2, int N) {
    int d = blockIdx.x * 8 + (threadIdx.x >> 5);
    if (d >= N) return;
    int l = threadIdx.x & 31;
    const __half2* y = (const __half2*)g_buf3;   // half[.][64]
    float2 acc = __half22float2(y[(size_t)d * 32 + l]);
    int e = g_off[d], e1 = g_off[d + 1];
    for (; e + 4 <= e1; e += 4) {
        int s0 = g_csr[e], s1 = g_csr[e + 1], s2 = g_csr[e + 2], s3 = g_csr[e + 3];
        float2 v0 = __half22float2(y[(size_t)s0 * 32 + l]);
        float2 v1 = __half22float2(y[(size_t)s1 * 32 + l]);
        float2 v2 = __half22float2(y[(size_t)s2 * 32 + l]);
        float2 v3 = __half22float2(y[(size_t)s3 * 32 + l]);
        acc.x += v0.x + v1.x + v2.x + v3.x;
        acc.y += v0.y + v1.y + v2.y + v3.y;
    }
    for (; e < e1; e++) {
        float2 v = __half22float2(y[(size_t)g_csr[e] * 32 + l]);
        acc.x += v.x; acc.y += v.y;
    }
    float s = g_dinv[d];
    const float2 b = ((const float2*)b2)[l];
    ((__half2*)g_buf1)[(size_t)d * 32 + l] =
        __floats2half2_rn(acc.x * s + b.x, acc.y * s + b.y);
}

// ---------------- fused head (h2 half) ----------------
__global__ __launch_bounds__(256)
void k_head(const int* __restrict__ batch, const float* __restrict__ fcW,
            const float* __restrict__ fcb, float* __restrict__ out, int N) {
    __shared__ int s_lo, s_hi;
    __shared__ float s_red[256];
    __shared__ float s_mean[64];
    __shared__ float s_logit[4];
    const int gph = blockIdx.x;
    const int tid = threadIdx.x;
    if (tid == 0) {
        int lo = 0, hi = N;
        while (lo < hi) { int m = (lo + hi) >> 1; if (batch[m] < gph) lo = m + 1; else hi = m; }
        s_lo = lo;
        int lo2 = lo, hi2 = N;
        while (lo2 < hi2) { int m = (lo2 + hi2) >> 1; if (batch[m] < gph + 1) lo2 = m + 1; else hi2 = m; }
        s_hi = lo2;
    }
    __syncthreads();
    const int lo = s_lo, hi = s_hi;
    const float inv = 1.f / fmaxf((float)(hi - lo), 1.f);
    const int f = tid & 63, sub = tid >> 6;
    const __half* h2 = (const __half*)g_buf1;
    float sum = 0.f;
    for (int i = lo + sub; i < hi; i += 4) sum += __half2float(h2[(size_t)i * 64 + f]);
    s_red[tid] = sum;
    __syncthreads();
    if (tid < 64) {
        float t = s_red[tid] + s_red[tid + 64] + s_red[tid + 128] + s_red[tid + 192];
        s_mean[tid] = t * inv;
    }
    __syncthreads();
    if (tid < 4) {
        float l = fcb[tid];
        #pragma unroll 8
        for (int k = 0; k < 64; k++) l += s_mean[k] * fcW[k * 4 + tid];
        s_logit[tid] = l;
    }
    __syncthreads();
    if (tid == 0) {
        float l0 = s_logit[0], l1 = s_logit[1], l2 = s_logit[2], l3 = s_logit[3];
        float m = fmaxf(fmaxf(l0, l1), fmaxf(l2, l3));
        float s = expf(l0 - m) + expf(l1 - m) + expf(l2 - m) + expf(l3 - m);
        float ls = m + logf(s);
        out[gph * 4 + 0] = l0 - ls;
        out[gph * 4 + 1] = l1 - ls;
        out[gph * 4 + 2] = l2 - ls;
        out[gph * 4 + 3] = l3 - ls;
    }
}

// ---------------- launch (forked capture stream: GEMM1 || CSR build) ----------------
extern "C" void kernel_launch(void* const* d_in, const int* in_sizes, int n_in,
                              void* d_out, int out_size) {
    const float* x     = (const float*)d_in[0];
    const int*   ei    = (const int*)d_in[1];
    const int*   batch = (const int*)d_in[2];
    const float* W1    = (const float*)d_in[3];
    const float* b1    = (const float*)d_in[4];
    const float* W2    = (const float*)d_in[5];
    const float* b2    = (const float*)d_in[6];
    const float* fcW   = (const float*)d_in[7];
    const float* fcb   = (const float*)d_in[8];
    float* out = (float*)d_out;

    const int N = in_sizes[0] / 256;
    const int E = in_sizes[1] / 2;
    const int G = out_size / 4;
    const int* src = ei;
    const int* dst = ei + E;

    static cudaStream_t s2 = [] {
        cudaStream_t s; cudaStreamCreateWithFlags(&s, cudaStreamNonBlocking); return s;
    }();
    static cudaEvent_t ev1 = [] {
        cudaEvent_t e; cudaEventCreateWithFlags(&e, cudaEventDisableTiming); return e;
    }();
    static cudaEvent_t ev2 = [] {
        cudaEvent_t e; cudaEventCreateWithFlags(&e, cudaEventDisableTiming); return e;
    }();

    float *b1p, *b2p, *b3p;
    int *degp;
    cudaGetSymbolAddress((void**)&b1p, g_buf1);
    cudaGetSymbolAddress((void**)&b2p, g_buf2);
    cudaGetSymbolAddress((void**)&b3p, g_buf3);
    cudaGetSymbolAddress((void**)&degp, g_deg);
    __half* y1h = (__half*)b1p;
    __half* h1h = (__half*)b2p;
    __half* y2h = (__half*)b3p;

    const int nb    = (N + 255) / 256;
    const int nscan = (N + 1023) / 1024;
    const int gm    = (N + 127) / 128;
    const int ga    = (N + 7) / 8;

    // fork: tensor branch (weights convert + GEMM1) on s2
    cudaEventRecord(ev1, 0);
    cudaStreamWaitEvent(s2, ev1, 0);
    k_wconv<<<160, 256, 0, s2>>>(W1, W2);
    gemm1_f16<<<gm, 256, 0, s2>>>(x, y1h, N);
    cudaEventRecord(ev2, s2);

    // prep branch (CSR build) on main stream
    cudaMemsetAsync(degp, 0, (size_t)N * sizeof(int), 0);
    k_count<<<1184, 256>>>(dst, E);
    k_scan1<<<nscan, 1024>>>(N);
    k_scan2<<<1, 128>>>(nscan);
    k_scan3<<<nb, 256>>>(N);
    k_fill<<<1184, 256>>>(src, dst, E);

    // join, then serial tail
    cudaStreamWaitEvent(0, ev2, 0);
    k_agg1<<<ga, 256>>>(b1, N);
    gemm2_f16<<<gm, 256>>>(h1h, y2h, N);
    k_agg2<<<ga, 256>>>(b2, N);
    k_head<<<G, 256>>>(batch, fcW, fcb, out, N);
}